// round 3
// baseline (speedup 1.0000x reference)
#include <cuda_runtime.h>

#define RD 64
#define UD 64
#define VD 64
#define HD 128
#define XD 64
#define NB 8
#define IJ 1024          // tokens per batch

// Kernel-B tiling
#define TM 128           // token tile
#define HC 64            // h chunk (HD split across hblk)
#define RRG 16           // rr per CTA (rr-split by 4)
#define VSP 132          // Vs row stride [v][m]
#define ACP 68           // Ach row stride [v][h]
#define W2P 68           // W2T row stride [h][x]
#define PSP 132          // Ps row stride [h][m]
#define RLP 132          // Rall row stride [rloc][m]

#define SM_FLOATS (VD*VSP + VD*ACP + HC*W2P + HC*PSP + RRG*RLP)
#define SMEM_B (SM_FLOATS * (int)sizeof(float))

// Scratch
__device__ float g_A[NB * RD * VD * HD];     // A[n][r][v][h], 16.8 MB (L2-resident)
__device__ float g_rT[NB * RD * IJ];         // r transposed: [n][rr][token], 2 MB

typedef unsigned long long u64;

__device__ __forceinline__ u64 pk2(float lo, float hi) {
    u64 r; asm("mov.b64 %0,{%1,%2};" : "=l"(r) : "f"(lo), "f"(hi)); return r;
}
__device__ __forceinline__ u64 dup2(float v) {
    u64 r; asm("mov.b64 %0,{%1,%1};" : "=l"(r) : "f"(v)); return r;
}
__device__ __forceinline__ void fma2(u64& d, u64 a, u64 b) {
    asm("fma.rn.f32x2 %0,%1,%2,%0;" : "+l"(d) : "l"(a), "l"(b));
}
__device__ __forceinline__ u64 mul2(u64 a, u64 b) {
    u64 r; asm("mul.rn.f32x2 %0,%1,%2;" : "=l"(r) : "l"(a), "l"(b)); return r;
}
__device__ __forceinline__ void upk(u64 v, float& lo, float& hi) {
    asm("mov.b64 {%0,%1},%2;" : "=f"(lo), "=f"(hi) : "l"(v));
}

// ---------------------------------------------------------------------------
// Transpose r: g_rT[n][rr][t] = r[n][t][rr]
// ---------------------------------------------------------------------------
__global__ __launch_bounds__(256) void kernR(const float* __restrict__ r) {
    const int n = blockIdx.x, rr = blockIdx.y;
    for (int t = threadIdx.x; t < IJ; t += 256)
        g_rT[(n * RD + rr) * IJ + t] = r[(n * IJ + t) * RD + rr];
}

// ---------------------------------------------------------------------------
// Kernel A: A[n,rr,v,h] = sum_u w1[rr,u,v,h]*u[n,rr,u,v]; also zeroes out.
// ---------------------------------------------------------------------------
__global__ __launch_bounds__(128) void kernA(const float* __restrict__ u,
                                             const float* __restrict__ w1,
                                             float* __restrict__ out) {
    const int rr = blockIdx.x;
    const int vv = blockIdx.y;
    const int h  = threadIdx.x;

    // zero output: 4096 CTAs * 128 threads = 524288 = out element count
    out[(blockIdx.y * RD + blockIdx.x) * 128 + threadIdx.x] = 0.f;

    __shared__ float us[NB][UD];
    for (int idx = threadIdx.x; idx < NB * UD; idx += 128) {
        int n = idx >> 6, uu = idx & 63;
        us[n][uu] = u[((n * RD + rr) * UD + uu) * VD + vv];
    }
    __syncthreads();

    float acc[NB];
#pragma unroll
    for (int n = 0; n < NB; n++) acc[n] = 0.f;

    const float* w1p = w1 + (rr * UD * VD + vv) * HD + h;
#pragma unroll 4
    for (int uu = 0; uu < UD; uu++) {
        float w = w1p[uu * (VD * HD)];
#pragma unroll
        for (int n = 0; n < NB; n++) acc[n] = fmaf(w, us[n][uu], acc[n]);
    }
#pragma unroll
    for (int n = 0; n < NB; n++)
        g_A[((n * RD + rr) * VD + vv) * HD + h] = acc[n];
}

// ---------------------------------------------------------------------------
// Kernel B: fused double GEMM, 128 threads, tile 128m x 64h, microtile 8m x 8c
// grid (8 token tiles, 8 n, 2 hblk * 4 rr-groups)
// ---------------------------------------------------------------------------
extern __shared__ float smem[];

__global__ __launch_bounds__(128, 2) void kernB(const float* __restrict__ v,
                                                const float* __restrict__ w2,
                                                float* __restrict__ out) {
    const int tile   = blockIdx.x;           // 0..7
    const int n      = blockIdx.y;           // 0..7
    const int z      = blockIdx.z;           // 0..7
    const int hblk   = z & 1;
    const int rr0    = (z >> 1) * RRG;
    const int token0 = tile * TM;
    const int tid    = threadIdx.x;
    const int mi = tid >> 3, ni = tid & 7;
    const int m0 = mi * 8, c0 = ni * 8;

    float* Vs   = smem;                      // [VD][VSP]   V^T: [v][m]
    float* Ach  = Vs   + VD * VSP;           // [VD][ACP]   A:   [v][h]
    float* W2T  = Ach  + VD * ACP;           // [HC][W2P]   w2^T:[h][x]
    float* Ps   = W2T  + HC * W2P;           // [HC][PSP]   P^T: [h][m]
    float* Rall = Ps   + HC * PSP;           // [RRG][RLP]  rT:  [rloc][m]

    // load V tile transposed (float4 reads, near-conflict-free scatter)
    {
        const int mq = tid >> 4;             // 0..7
        const int kq = (tid & 15) * 4;       // 0..60
#pragma unroll 4
        for (int i = 0; i < 16; i++) {
            int m = i * 8 + mq;
            float4 vv = *(const float4*)&v[(n * IJ + token0 + m) * VD + kq];
            Vs[(kq + 0) * VSP + m] = vv.x;
            Vs[(kq + 1) * VSP + m] = vv.y;
            Vs[(kq + 2) * VSP + m] = vv.z;
            Vs[(kq + 3) * VSP + m] = vv.w;
        }
    }
    // load r rows for this rr-group (already transposed: contiguous)
#pragma unroll 4
    for (int idx = tid; idx < RRG * TM; idx += 128) {
        int j = idx >> 7, m = idx & 127;
        Rall[j * RLP + m] = g_rT[(n * RD + rr0 + j) * IJ + token0 + m];
    }

    u64 o2[4][8];
#pragma unroll
    for (int a = 0; a < 4; a++)
#pragma unroll
        for (int b = 0; b < 8; b++) o2[a][b] = 0ull;

    const int h0g = hblk * HC;
    const float* Abase = g_A + (n * RD * VD) * HD;

    for (int rloc = 0; rloc < RRG; rloc++) {
        const int rr = rr0 + rloc;
        __syncthreads();    // previous iter consumers of Ach/W2T/Ps done (also covers init loads)
        {
            const float* Ab = Abase + rr * VD * HD + h0g;
#pragma unroll 4
            for (int i = 0; i < 32; i++) {
                int idx = tid + i * 128;
                int k = idx >> 6, hh = idx & 63;
                Ach[k * ACP + hh] = Ab[k * HD + hh];
            }
            const float* Wb = w2 + rr * HD + h0g;
#pragma unroll 4
            for (int i = 0; i < 32; i++) {
                int idx = tid + i * 128;
                int x = idx >> 6, hh = idx & 63;
                W2T[hh * W2P + x] = Wb[x * (RD * HD) + hh];
            }
        }
        __syncthreads();

        // ---- stage 1: P[128m x 64h], K = VD; 8m(4 pairs) x 8h per thread ----
        u64 p2[4][8];
#pragma unroll
        for (int a = 0; a < 4; a++)
#pragma unroll
            for (int b = 0; b < 8; b++) p2[a][b] = 0ull;

#pragma unroll 4
        for (int k = 0; k < VD; k++) {
            const float* vrow = &Vs[k * VSP + m0];
            ulonglong2 vA = *(const ulonglong2*)(vrow);
            ulonglong2 vB = *(const ulonglong2*)(vrow + 4);
            u64 pa[4] = {vA.x, vA.y, vB.x, vB.y};
            float4 a0 = *(const float4*)&Ach[k * ACP + c0];
            float4 a1 = *(const float4*)&Ach[k * ACP + c0 + 4];
            u64 bb[8] = {dup2(a0.x), dup2(a0.y), dup2(a0.z), dup2(a0.w),
                         dup2(a1.x), dup2(a1.y), dup2(a1.z), dup2(a1.w)};
#pragma unroll
            for (int a = 0; a < 4; a++)
#pragma unroll
                for (int b = 0; b < 8; b++)
                    fma2(p2[a][b], pa[a], bb[b]);
        }

        // relu + r-scale, store transposed [h][m]
        {
            const float* rrow = &Rall[rloc * RLP + m0];
            ulonglong2 rA = *(const ulonglong2*)(rrow);
            ulonglong2 rB = *(const ulonglong2*)(rrow + 4);
            u64 rp[4] = {rA.x, rA.y, rB.x, rB.y};
#pragma unroll
            for (int a = 0; a < 4; a++)
#pragma unroll
                for (int b = 0; b < 8; b++) {
                    float lo, hi; upk(p2[a][b], lo, hi);
                    lo = fmaxf(lo, 0.f); hi = fmaxf(hi, 0.f);
                    *(u64*)&Ps[(c0 + b) * PSP + m0 + 2 * a] = mul2(pk2(lo, hi), rp[a]);
                }
        }
        __syncthreads();

        // ---- stage 2: OUT += P @ W2^T, K = HC; 8m(4 pairs) x 8x per thread ----
#pragma unroll 4
        for (int k = 0; k < HC; k++) {
            const float* prow = &Ps[k * PSP + m0];
            ulonglong2 pA = *(const ulonglong2*)(prow);
            ulonglong2 pB = *(const ulonglong2*)(prow + 4);
            u64 qa[4] = {pA.x, pA.y, pB.x, pB.y};
            float4 w0 = *(const float4*)&W2T[k * W2P + c0];
            float4 w1v = *(const float4*)&W2T[k * W2P + c0 + 4];
            u64 bb[8] = {dup2(w0.x), dup2(w0.y), dup2(w0.z), dup2(w0.w),
                         dup2(w1v.x), dup2(w1v.y), dup2(w1v.z), dup2(w1v.w)};
#pragma unroll
            for (int a = 0; a < 4; a++)
#pragma unroll
                for (int b = 0; b < 8; b++)
                    fma2(o2[a][b], qa[a], bb[b]);
        }
    }

    // epilogue: 8 partial CTAs (2 hblk x 4 rrg) accumulate per out element
#pragma unroll
    for (int a = 0; a < 4; a++)
#pragma unroll
        for (int b = 0; b < 8; b++) {
            float lo, hi; upk(o2[a][b], lo, hi);
            int m = n * IJ + token0 + m0 + 2 * a;
            atomicAdd(&out[m * XD + c0 + b], lo);
            atomicAdd(&out[(m + 1) * XD + c0 + b], hi);
        }
}

// ---------------------------------------------------------------------------
extern "C" void kernel_launch(void* const* d_in, const int* in_sizes, int n_in,
                              void* d_out, int out_size) {
    const float* r  = (const float*)d_in[0];
    const float* u  = (const float*)d_in[1];
    const float* v  = (const float*)d_in[2];
    const float* w1 = (const float*)d_in[3];
    const float* w2 = (const float*)d_in[4];
    float* out = (float*)d_out;
    (void)in_sizes; (void)n_in; (void)out_size;

    cudaFuncSetAttribute(kernB, cudaFuncAttributeMaxDynamicSharedMemorySize, SMEM_B);

    kernR<<<dim3(NB, RD), 256>>>(r);
    kernA<<<dim3(RD, VD), 128>>>(u, w1, out);
    kernB<<<dim3(8, NB, 8), 128, SMEM_B>>>(v, w2, out);
}

// round 4
// speedup vs baseline: 1.1316x; 1.1316x over previous
#include <cuda_runtime.h>

#define RD 64
#define UD 64
#define VD 64
#define HD 128
#define XD 64
#define NB 8
#define IJ 1024          // tokens per batch

// Kernel-B tiling: token tile 64, h-chunk 64, rr-groups of 32
#define TM 64
#define HC 64
#define RRG 32
#define VSP 68           // Vs row stride [v][m]
#define ACP 68           // Ach row stride [v][h]
#define W2P 65           // W2T row stride [h][x] (transposed store conflict-free)
#define PSP 66           // Ps row stride [h][m]

#define SM_FLOATS (VD*VSP + VD*ACP + HC*W2P + HC*PSP)
#define SMEM_B (SM_FLOATS * (int)sizeof(float))

// Scratch
__device__ float g_A[NB * RD * VD * HD];     // A[n][r][v][h], 16.8 MB
__device__ float g_rT[NB * RD * IJ];         // r^T: [n][rr][token], 2 MB (L2-resident)

typedef unsigned long long u64;

__device__ __forceinline__ u64 pk2(float lo, float hi) {
    u64 r; asm("mov.b64 %0,{%1,%2};" : "=l"(r) : "f"(lo), "f"(hi)); return r;
}
__device__ __forceinline__ u64 dup2(float v) {
    u64 r; asm("mov.b64 %0,{%1,%1};" : "=l"(r) : "f"(v)); return r;
}
__device__ __forceinline__ void fma2(u64& d, u64 a, u64 b) {
    asm("fma.rn.f32x2 %0,%1,%2,%0;" : "+l"(d) : "l"(a), "l"(b));
}
__device__ __forceinline__ u64 mul2(u64 a, u64 b) {
    u64 r; asm("mul.rn.f32x2 %0,%1,%2;" : "=l"(r) : "l"(a), "l"(b)); return r;
}
__device__ __forceinline__ void upk(u64 v, float& lo, float& hi) {
    asm("mov.b64 {%0,%1},%2;" : "=f"(lo), "=f"(hi) : "l"(v));
}

// ---------------------------------------------------------------------------
// Transpose r: g_rT[n][rr][t] = r[n][t][rr]
// ---------------------------------------------------------------------------
__global__ __launch_bounds__(256) void kernR(const float* __restrict__ r) {
    const int n = blockIdx.x, rr = blockIdx.y;
    for (int t = threadIdx.x; t < IJ; t += 256)
        g_rT[(n * RD + rr) * IJ + t] = r[(n * IJ + t) * RD + rr];
}

// ---------------------------------------------------------------------------
// Kernel A: A[n,rr,v,h] = sum_u w1[rr,u,v,h]*u[n,rr,u,v]; also zeroes out.
// ---------------------------------------------------------------------------
__global__ __launch_bounds__(128) void kernA(const float* __restrict__ u,
                                             const float* __restrict__ w1,
                                             float* __restrict__ out) {
    const int rr = blockIdx.x;
    const int vv = blockIdx.y;
    const int h  = threadIdx.x;

    // zero output: 4096 CTAs * 128 threads = 524288 = out element count
    out[(blockIdx.y * RD + blockIdx.x) * 128 + threadIdx.x] = 0.f;

    __shared__ float us[NB][UD];
    for (int idx = threadIdx.x; idx < NB * UD; idx += 128) {
        int n = idx >> 6, uu = idx & 63;
        us[n][uu] = u[((n * RD + rr) * UD + uu) * VD + vv];
    }
    __syncthreads();

    float acc[NB];
#pragma unroll
    for (int n = 0; n < NB; n++) acc[n] = 0.f;

    const float* w1p = w1 + (rr * UD * VD + vv) * HD + h;
#pragma unroll 4
    for (int uu = 0; uu < UD; uu++) {
        float w = w1p[uu * (VD * HD)];
#pragma unroll
        for (int n = 0; n < NB; n++) acc[n] = fmaf(w, us[n][uu], acc[n]);
    }
#pragma unroll
    for (int n = 0; n < NB; n++)
        g_A[((n * RD + rr) * VD + vv) * HD + h] = acc[n];
}

// ---------------------------------------------------------------------------
// Kernel B: fused double GEMM per (token tile, n, h-half, rr-group).
// 128 threads, tile 64m x 64c, microtile 8m(4 pairs) x 4c, packed f32x2 FMAs.
// grid (16, 8, 4) = 512 CTAs, 32 rr per CTA, 3 CTAs/SM.
// ---------------------------------------------------------------------------
extern __shared__ float smem[];

__global__ __launch_bounds__(128, 3) void kernB(const float* __restrict__ v,
                                                const float* __restrict__ w2,
                                                float* __restrict__ out) {
    const int tile   = blockIdx.x;           // 0..15
    const int n      = blockIdx.y;           // 0..7
    const int z      = blockIdx.z;           // 0..3
    const int hblk   = z & 1;
    const int rr0    = (z >> 1) * RRG;
    const int token0 = tile * TM;
    const int tid    = threadIdx.x;
    const int mi = tid >> 4, ni = tid & 15;
    const int m0 = mi * 8, c0 = ni * 4;

    float* Vs  = smem;                       // [VD][VSP]  V^T:  [v][m]
    float* Ach = Vs  + VD * VSP;             // [VD][ACP]  A:    [v][h]
    float* W2T = Ach + VD * ACP;             // [HC][W2P]  w2^T: [h][x]
    float* Ps  = W2T + HC * W2P;             // [HC][PSP]  P^T:  [h][m]

    // load V tile transposed
    for (int idx = tid; idx < TM * VD; idx += 128) {
        int m = idx >> 6, k = idx & 63;
        Vs[k * VSP + m] = v[(n * IJ + token0 + m) * VD + k];
    }

    u64 o2[4][4];
#pragma unroll
    for (int a = 0; a < 4; a++)
#pragma unroll
        for (int b = 0; b < 4; b++) o2[a][b] = 0ull;

    const int h0g = hblk * HC;
    const float* Abase = g_A + (n * RD * VD) * HD;
    const float* rTbase = g_rT + (n * RD) * IJ + token0 + m0;

    for (int rloc = 0; rloc < RRG; rloc++) {
        const int rr = rr0 + rloc;

        // prefetch r row for this rr (L2-resident; consumed after stage 1)
        ulonglong2 rA = *(const ulonglong2*)(rTbase + rr * IJ);
        ulonglong2 rB = *(const ulonglong2*)(rTbase + rr * IJ + 4);

        __syncthreads();   // previous iteration's consumers of Ach/W2T/Ps done
        {
            const float* Ab = Abase + rr * VD * HD + h0g;
#pragma unroll 8
            for (int i = 0; i < 32; i++) {
                int idx = tid + i * 128;
                int k = idx >> 6, hh = idx & 63;
                Ach[k * ACP + hh] = Ab[k * HD + hh];
            }
            const float* Wb = w2 + rr * HD + h0g;
#pragma unroll 8
            for (int i = 0; i < 32; i++) {
                int idx = tid + i * 128;
                int x = idx >> 6, hh = idx & 63;
                W2T[hh * W2P + x] = Wb[x * (RD * HD) + hh];
            }
        }
        __syncthreads();

        // ---- stage 1: P tile (64m x 64h), K = VD, 8m(4 pairs) x 4h / thread ----
        u64 p2[4][4];
#pragma unroll
        for (int a = 0; a < 4; a++)
#pragma unroll
            for (int b = 0; b < 4; b++) p2[a][b] = 0ull;

#pragma unroll 8
        for (int k = 0; k < VD; k++) {
            const float* vrow = &Vs[k * VSP + m0];
            ulonglong2 vA = *(const ulonglong2*)(vrow);
            ulonglong2 vB = *(const ulonglong2*)(vrow + 4);
            u64 pa[4] = {vA.x, vA.y, vB.x, vB.y};
            float4 aa = *(const float4*)&Ach[k * ACP + c0];
            u64 b0 = dup2(aa.x), b1 = dup2(aa.y), b2 = dup2(aa.z), b3 = dup2(aa.w);
#pragma unroll
            for (int a = 0; a < 4; a++) {
                fma2(p2[a][0], pa[a], b0);
                fma2(p2[a][1], pa[a], b1);
                fma2(p2[a][2], pa[a], b2);
                fma2(p2[a][3], pa[a], b3);
            }
        }

        // relu + r-scale, store transposed (pairs along m) for stage 2
        {
            u64 rp[4] = {rA.x, rA.y, rB.x, rB.y};
#pragma unroll
            for (int a = 0; a < 4; a++)
#pragma unroll
                for (int b = 0; b < 4; b++) {
                    float lo, hi; upk(p2[a][b], lo, hi);
                    lo = fmaxf(lo, 0.f); hi = fmaxf(hi, 0.f);
                    *(u64*)&Ps[(c0 + b) * PSP + m0 + 2 * a] = mul2(pk2(lo, hi), rp[a]);
                }
        }
        __syncthreads();

        // ---- stage 2: OUT += P @ W2^T, K = HC, 8m(4 pairs) x 4x / thread ----
#pragma unroll 8
        for (int k = 0; k < HC; k++) {
            const float* prow = &Ps[k * PSP + m0];
            u64 q0 = *(const u64*)(prow);
            u64 q1 = *(const u64*)(prow + 2);
            u64 q2 = *(const u64*)(prow + 4);
            u64 q3 = *(const u64*)(prow + 6);
            u64 qa[4] = {q0, q1, q2, q3};
            const float* wrow = &W2T[k * W2P + c0];
            u64 b0 = dup2(wrow[0]), b1 = dup2(wrow[1]), b2 = dup2(wrow[2]), b3 = dup2(wrow[3]);
#pragma unroll
            for (int a = 0; a < 4; a++) {
                fma2(o2[a][0], qa[a], b0);
                fma2(o2[a][1], qa[a], b1);
                fma2(o2[a][2], qa[a], b2);
                fma2(o2[a][3], qa[a], b3);
            }
        }
    }

    // epilogue: 4 partial CTAs (2 hblk x 2 rr-groups) accumulate per out element
#pragma unroll
    for (int a = 0; a < 4; a++)
#pragma unroll
        for (int b = 0; b < 4; b++) {
            float lo, hi; upk(o2[a][b], lo, hi);
            int m = n * IJ + token0 + m0 + 2 * a;
            atomicAdd(&out[m * XD + c0 + b], lo);
            atomicAdd(&out[(m + 1) * XD + c0 + b], hi);
        }
}

// ---------------------------------------------------------------------------
extern "C" void kernel_launch(void* const* d_in, const int* in_sizes, int n_in,
                              void* d_out, int out_size) {
    const float* r  = (const float*)d_in[0];
    const float* u  = (const float*)d_in[1];
    const float* v  = (const float*)d_in[2];
    const float* w1 = (const float*)d_in[3];
    const float* w2 = (const float*)d_in[4];
    float* out = (float*)d_out;
    (void)in_sizes; (void)n_in; (void)out_size;

    cudaFuncSetAttribute(kernB, cudaFuncAttributeMaxDynamicSharedMemorySize, SMEM_B);

    kernR<<<dim3(NB, RD), 256>>>(r);
    kernA<<<dim3(RD, VD), 128>>>(u, w1, out);
    kernB<<<dim3(16, NB, 4), 128, SMEM_B>>>(v, w2, out);
}

// round 5
// speedup vs baseline: 1.3684x; 1.2092x over previous
#include <cuda_runtime.h>

#define RD 64
#define UD 64
#define VD 64
#define HD 128
#define XD 64
#define NB 8
#define IJ 1024          // tokens per batch

// Kernel-B tiling: token tile 128, h-chunk 64, rr-groups of 32
#define TM 128
#define HC 64
#define RRG 32
#define VSP 132          // Vs row stride [v][m]   (528B, 16B-aligned rows)
#define ACP 68           // Ach row stride [v][h]  (272B, 16B-aligned rows)
#define W2P 65           // W2T row stride [h][x]  (conflict-free transposed fill)
#define PSP 130          // Ps row stride [h][m]   (520B, 8B-aligned rows)

#define SM_FLOATS (VD*VSP + VD*ACP + HC*W2P + HC*PSP)
#define SMEM_B (SM_FLOATS * (int)sizeof(float))

// Scratch
__device__ float g_A[NB * RD * VD * HD];     // A[n][r][v][h], 16.8 MB
__device__ float g_rT[NB * RD * IJ];         // r^T: [n][rr][token], 2 MB (L2-resident)

typedef unsigned long long u64;

__device__ __forceinline__ u64 pk2(float lo, float hi) {
    u64 r; asm("mov.b64 %0,{%1,%2};" : "=l"(r) : "f"(lo), "f"(hi)); return r;
}
__device__ __forceinline__ u64 dup2(float v) {
    u64 r; asm("mov.b64 %0,{%1,%1};" : "=l"(r) : "f"(v)); return r;
}
__device__ __forceinline__ void fma2(u64& d, u64 a, u64 b) {
    asm("fma.rn.f32x2 %0,%1,%2,%0;" : "+l"(d) : "l"(a), "l"(b));
}
__device__ __forceinline__ u64 mul2(u64 a, u64 b) {
    u64 r; asm("mul.rn.f32x2 %0,%1,%2;" : "=l"(r) : "l"(a), "l"(b)); return r;
}
__device__ __forceinline__ void upk(u64 v, float& lo, float& hi) {
    asm("mov.b64 {%0,%1},%2;" : "=f"(lo), "=f"(hi) : "l"(v));
}

// ---------------------------------------------------------------------------
// Transpose r: g_rT[n][rr][t] = r[n][t][rr]
// ---------------------------------------------------------------------------
__global__ __launch_bounds__(256) void kernR(const float* __restrict__ r) {
    const int n = blockIdx.x, rr = blockIdx.y;
    for (int t = threadIdx.x; t < IJ; t += 256)
        g_rT[(n * RD + rr) * IJ + t] = r[(n * IJ + t) * RD + rr];
}

// ---------------------------------------------------------------------------
// Kernel A: A[n,rr,v,h] = sum_u w1[rr,u,v,h]*u[n,rr,u,v]; also zeroes out.
// ---------------------------------------------------------------------------
__global__ __launch_bounds__(128) void kernA(const float* __restrict__ u,
                                             const float* __restrict__ w1,
                                             float* __restrict__ out) {
    const int rr = blockIdx.x;
    const int vv = blockIdx.y;
    const int h  = threadIdx.x;

    // zero output: 4096 CTAs * 128 threads = 524288 = out element count
    out[(blockIdx.y * RD + blockIdx.x) * 128 + threadIdx.x] = 0.f;

    __shared__ float us[NB][UD];
    for (int idx = threadIdx.x; idx < NB * UD; idx += 128) {
        int n = idx >> 6, uu = idx & 63;
        us[n][uu] = u[((n * RD + rr) * UD + uu) * VD + vv];
    }
    __syncthreads();

    float acc[NB];
#pragma unroll
    for (int n = 0; n < NB; n++) acc[n] = 0.f;

    const float* w1p = w1 + (rr * UD * VD + vv) * HD + h;
#pragma unroll 4
    for (int uu = 0; uu < UD; uu++) {
        float w = w1p[uu * (VD * HD)];
#pragma unroll
        for (int n = 0; n < NB; n++) acc[n] = fmaf(w, us[n][uu], acc[n]);
    }
#pragma unroll
    for (int n = 0; n < NB; n++)
        g_A[((n * RD + rr) * VD + vv) * HD + h] = acc[n];
}

// ---------------------------------------------------------------------------
// Kernel B: fused double GEMM. 256 threads, tile 128m x 64c,
// microtile 8m(4 pairs) x 4c, packed f32x2 FMAs.
// grid (8 token tiles, 8 n, 2 hblk x 2 rr-groups) = 256 CTAs, 2 CTAs/SM.
// ---------------------------------------------------------------------------
extern __shared__ float smem[];

__global__ __launch_bounds__(256, 2) void kernB(const float* __restrict__ v,
                                                const float* __restrict__ w2,
                                                float* __restrict__ out) {
    const int tile   = blockIdx.x;           // 0..7
    const int n      = blockIdx.y;           // 0..7
    const int z      = blockIdx.z;           // 0..3
    const int hblk   = z & 1;
    const int rr0    = (z >> 1) * RRG;
    const int token0 = tile * TM;
    const int tid    = threadIdx.x;
    const int mi = tid >> 4, ni = tid & 15;
    const int m0 = mi * 8, c0 = ni * 4;

    float* Vs  = smem;                       // [VD][VSP]  V^T:  [v][m]
    float* Ach = Vs  + VD * VSP;             // [VD][ACP]  A:    [v][h]
    float* W2T = Ach + VD * ACP;             // [HC][W2P]  w2^T: [h][x]
    float* Ps  = W2T + HC * W2P;             // [HC][PSP]  P^T:  [h][m]

    // load V tile transposed (float4 global reads)
    {
        const int mq = tid >> 4;             // 0..15
        const int kq = (tid & 15) * 4;       // 0..60
#pragma unroll
        for (int i = 0; i < 8; i++) {
            int m = i * 16 + mq;
            float4 vv = *(const float4*)&v[(n * IJ + token0 + m) * VD + kq];
            Vs[(kq + 0) * VSP + m] = vv.x;
            Vs[(kq + 1) * VSP + m] = vv.y;
            Vs[(kq + 2) * VSP + m] = vv.z;
            Vs[(kq + 3) * VSP + m] = vv.w;
        }
    }

    u64 o2[4][4];
#pragma unroll
    for (int a = 0; a < 4; a++)
#pragma unroll
        for (int b = 0; b < 4; b++) o2[a][b] = 0ull;

    const int h0g = hblk * HC;
    const float* Abase  = g_A + (n * RD * VD) * HD;
    const float* rTbase = g_rT + (n * RD) * IJ + token0 + m0;

    for (int rloc = 0; rloc < RRG; rloc++) {
        const int rr = rr0 + rloc;

        // prefetch r row for this rr (L2-resident; consumed after stage 1)
        ulonglong2 rA = *(const ulonglong2*)(rTbase + rr * IJ);
        ulonglong2 rB = *(const ulonglong2*)(rTbase + rr * IJ + 4);

        __syncthreads();   // previous iteration's consumers of Ach/W2T/Ps done
        {
            const float* Ab = Abase + rr * VD * HD + h0g;
#pragma unroll
            for (int i = 0; i < 4; i++) {
                int qi = tid + i * 256;              // 0..1023
                int k = qi >> 4, hq = (qi & 15) * 4;
                *(float4*)&Ach[k * ACP + hq] = *(const float4*)&Ab[k * HD + hq];
            }
            const float* Wb = w2 + rr * HD + h0g;
#pragma unroll
            for (int i = 0; i < 4; i++) {
                int qi = tid + i * 256;
                int x = qi >> 4, hq = (qi & 15) * 4;
                float4 wv = *(const float4*)&Wb[x * (RD * HD) + hq];
                W2T[(hq + 0) * W2P + x] = wv.x;
                W2T[(hq + 1) * W2P + x] = wv.y;
                W2T[(hq + 2) * W2P + x] = wv.z;
                W2T[(hq + 3) * W2P + x] = wv.w;
            }
        }
        __syncthreads();

        // ---- stage 1: P tile (128m x 64h), K = VD, 8m(4 pairs) x 4h / thread ----
        u64 p2[4][4];
#pragma unroll
        for (int a = 0; a < 4; a++)
#pragma unroll
            for (int b = 0; b < 4; b++) p2[a][b] = 0ull;

#pragma unroll 8
        for (int k = 0; k < VD; k++) {
            const float* vrow = &Vs[k * VSP + m0];
            ulonglong2 vA = *(const ulonglong2*)(vrow);
            ulonglong2 vB = *(const ulonglong2*)(vrow + 4);
            u64 pa[4] = {vA.x, vA.y, vB.x, vB.y};
            float4 aa = *(const float4*)&Ach[k * ACP + c0];
            u64 b0 = dup2(aa.x), b1 = dup2(aa.y), b2 = dup2(aa.z), b3 = dup2(aa.w);
#pragma unroll
            for (int a = 0; a < 4; a++) {
                fma2(p2[a][0], pa[a], b0);
                fma2(p2[a][1], pa[a], b1);
                fma2(p2[a][2], pa[a], b2);
                fma2(p2[a][3], pa[a], b3);
            }
        }

        // relu + r-scale, store transposed (pairs along m) for stage 2
        {
            u64 rp[4] = {rA.x, rA.y, rB.x, rB.y};
#pragma unroll
            for (int a = 0; a < 4; a++)
#pragma unroll
                for (int b = 0; b < 4; b++) {
                    float lo, hi; upk(p2[a][b], lo, hi);
                    lo = fmaxf(lo, 0.f); hi = fmaxf(hi, 0.f);
                    *(u64*)&Ps[(c0 + b) * PSP + m0 + 2 * a] = mul2(pk2(lo, hi), rp[a]);
                }
        }
        __syncthreads();

        // ---- stage 2: OUT += P @ W2^T, K = HC, 8m(4 pairs) x 4x / thread ----
#pragma unroll 8
        for (int k = 0; k < HC; k++) {
            const float* prow = &Ps[k * PSP + m0];
            u64 q0 = *(const u64*)(prow);
            u64 q1 = *(const u64*)(prow + 2);
            u64 q2 = *(const u64*)(prow + 4);
            u64 q3 = *(const u64*)(prow + 6);
            u64 qa[4] = {q0, q1, q2, q3};
            const float* wrow = &W2T[k * W2P + c0];
            u64 b0 = dup2(wrow[0]), b1 = dup2(wrow[1]), b2 = dup2(wrow[2]), b3 = dup2(wrow[3]);
#pragma unroll
            for (int a = 0; a < 4; a++) {
                fma2(o2[a][0], qa[a], b0);
                fma2(o2[a][1], qa[a], b1);
                fma2(o2[a][2], qa[a], b2);
                fma2(o2[a][3], qa[a], b3);
            }
        }
    }

    // epilogue: 4 partial CTAs (2 hblk x 2 rr-groups) accumulate per out element
#pragma unroll
    for (int a = 0; a < 4; a++)
#pragma unroll
        for (int b = 0; b < 4; b++) {
            float lo, hi; upk(o2[a][b], lo, hi);
            int m = n * IJ + token0 + m0 + 2 * a;
            atomicAdd(&out[m * XD + c0 + b], lo);
            atomicAdd(&out[(m + 1) * XD + c0 + b], hi);
        }
}

// ---------------------------------------------------------------------------
extern "C" void kernel_launch(void* const* d_in, const int* in_sizes, int n_in,
                              void* d_out, int out_size) {
    const float* r  = (const float*)d_in[0];
    const float* u  = (const float*)d_in[1];
    const float* v  = (const float*)d_in[2];
    const float* w1 = (const float*)d_in[3];
    const float* w2 = (const float*)d_in[4];
    float* out = (float*)d_out;
    (void)in_sizes; (void)n_in; (void)out_size;

    cudaFuncSetAttribute(kernB, cudaFuncAttributeMaxDynamicSharedMemorySize, SMEM_B);

    kernR<<<dim3(NB, RD), 256>>>(r);
    kernA<<<dim3(RD, VD), 128>>>(u, w1, out);
    kernB<<<dim3(8, NB, 4), 256, SMEM_B>>>(v, w2, out);
}

// round 7
// speedup vs baseline: 2.1539x; 1.5741x over previous
#include <cuda_runtime.h>
#include <cuda_bf16.h>
#include <cstdint>

#define RD 64
#define UD 64
#define VD 64
#define HD 128
#define XD 64
#define NB 8
#define IJ 1024
#define TM 64            // token tile
#define HC 64            // h per CTA (hblk)
#define RRG 32           // rr per CTA

// smem: 8 bf16 tiles [64 rows][72 cols] (row stride 144B, LDSM conflict-free)
#define ROWB 144
#define TILEB (64 * ROWB)          // 9216
#define SOFF_VHI 0
#define SOFF_VLO (1 * TILEB)
#define SOFF_AHI (2 * TILEB)
#define SOFF_ALO (3 * TILEB)
#define SOFF_WHI (4 * TILEB)
#define SOFF_WLO (5 * TILEB)
#define SOFF_PHI (6 * TILEB)
#define SOFF_PLO (7 * TILEB)
#define SMEM_TOTAL (8 * TILEB)     // 73728

// ---------------- gmem scratch ----------------
__device__ float g_A[NB * RD * VD * HD];                       // fp32 A, 16.8MB
__device__ float g_rT[NB * RD * IJ];                           // r^T, 2MB
__device__ __align__(16) unsigned short g_ahi[NB * RD * HD * VD];  // A split [n][rr][h][v]
__device__ __align__(16) unsigned short g_alo[NB * RD * HD * VD];
__device__ __align__(16) unsigned short g_vhi[NB * IJ * VD];       // V split [n][m][v]
__device__ __align__(16) unsigned short g_vlo[NB * IJ * VD];
__device__ __align__(16) unsigned short g_w2hi[RD * XD * HD];      // w2 split [rr][x][h]
__device__ __align__(16) unsigned short g_w2lo[RD * XD * HD];

// ---------------- helpers ----------------
__device__ __forceinline__ uint32_t smem_u32(const void* p) {
    uint32_t a;
    asm("{ .reg .u64 t; cvta.to.shared.u64 t, %1; cvt.u32.u64 %0, t; }" : "=r"(a) : "l"(p));
    return a;
}
__device__ __forceinline__ void ldsm4(uint32_t& r0, uint32_t& r1, uint32_t& r2, uint32_t& r3,
                                      uint32_t addr) {
    asm volatile("ldmatrix.sync.aligned.m8n8.x4.shared.b16 {%0,%1,%2,%3}, [%4];"
                 : "=r"(r0), "=r"(r1), "=r"(r2), "=r"(r3) : "r"(addr));
}
__device__ __forceinline__ void mma_bf16(float* d, uint32_t a0, uint32_t a1, uint32_t a2,
                                         uint32_t a3, uint32_t b0, uint32_t b1) {
    asm volatile(
        "mma.sync.aligned.m16n8k16.row.col.f32.bf16.bf16.f32 "
        "{%0,%1,%2,%3}, {%4,%5,%6,%7}, {%8,%9}, {%0,%1,%2,%3};"
        : "+f"(d[0]), "+f"(d[1]), "+f"(d[2]), "+f"(d[3])
        : "r"(a0), "r"(a1), "r"(a2), "r"(a3), "r"(b0), "r"(b1));
}
__device__ __forceinline__ void splitf(float x, unsigned short& hi, unsigned short& lo) {
    __nv_bfloat16 h = __float2bfloat16(x);
    __nv_bfloat16 l = __float2bfloat16(x - __bfloat162float(h));
    hi = __bfloat16_as_ushort(h);
    lo = __bfloat16_as_ushort(l);
}
__device__ __forceinline__ void split2(float p0, float p1, uint32_t& hp, uint32_t& lp) {
    unsigned short h0, l0, h1, l1;
    splitf(p0, h0, l0);
    splitf(p1, h1, l1);
    hp = ((uint32_t)h1 << 16) | h0;
    lp = ((uint32_t)l1 << 16) | l0;
}

// K=64 GEMM fragment loop: acc[8][4] covers 16m x 64n (8 n-tiles of 8).
// A operand smem [64 rows m][72], B operand smem [64 rows n][72].
__device__ __forceinline__ void gemm64(float acc[8][4], uint32_t abase, uint32_t bbase,
                                       int m0, int lane) {
    const uint32_t aaddr = abase + (uint32_t)(m0 + (lane & 15)) * ROWB
                         + (uint32_t)((lane >> 4) << 3) * 2;
    const uint32_t baddr = bbase + (uint32_t)(((lane >> 4) << 3) + (lane & 7)) * ROWB
                         + (uint32_t)(((lane >> 3) & 1) << 3) * 2;
#pragma unroll
    for (int k0 = 0; k0 < 64; k0 += 16) {
        uint32_t a0, a1, a2, a3;
        ldsm4(a0, a1, a2, a3, aaddr + k0 * 2);
#pragma unroll
        for (int nt = 0; nt < 4; nt++) {
            uint32_t b0, b1, b2, b3;
            ldsm4(b0, b1, b2, b3, baddr + nt * 16 * ROWB + k0 * 2);
            mma_bf16(acc[2 * nt],     a0, a1, a2, a3, b0, b1);
            mma_bf16(acc[2 * nt + 1], a0, a1, a2, a3, b2, b3);
        }
    }
}

// ---------------------------------------------------------------------------
// kernR: g_rT[n][rr][t] = r[n][t][rr]
// ---------------------------------------------------------------------------
__global__ __launch_bounds__(256) void kernR(const float* __restrict__ r) {
    const int n = blockIdx.x, rr = blockIdx.y;
    for (int t = threadIdx.x; t < IJ; t += 256)
        g_rT[(n * RD + rr) * IJ + t] = r[(n * IJ + t) * RD + rr];
}

// ---------------------------------------------------------------------------
// kernA: A[n,rr,v,h] = sum_u w1*u (fp32, g_A); also zeroes the output.
// ---------------------------------------------------------------------------
__global__ __launch_bounds__(128) void kernA(const float* __restrict__ u,
                                             const float* __restrict__ w1,
                                             float* __restrict__ out) {
    const int rr = blockIdx.x, vv = blockIdx.y, h = threadIdx.x;
    out[(blockIdx.y * RD + blockIdx.x) * 128 + threadIdx.x] = 0.f;

    __shared__ float us[NB][UD];
    for (int idx = threadIdx.x; idx < NB * UD; idx += 128) {
        int n = idx >> 6, uu = idx & 63;
        us[n][uu] = u[((n * RD + rr) * UD + uu) * VD + vv];
    }
    __syncthreads();

    float acc[NB];
#pragma unroll
    for (int n = 0; n < NB; n++) acc[n] = 0.f;
    const float* w1p = w1 + (rr * UD * VD + vv) * HD + h;
#pragma unroll 4
    for (int uu = 0; uu < UD; uu++) {
        float w = w1p[uu * (VD * HD)];
#pragma unroll
        for (int n = 0; n < NB; n++) acc[n] = fmaf(w, us[n][uu], acc[n]);
    }
#pragma unroll
    for (int n = 0; n < NB; n++)
        g_A[((n * RD + rr) * VD + vv) * HD + h] = acc[n];
}

// ---------------------------------------------------------------------------
// kernT: transpose + split g_A[n][rr][v][h] -> g_ahi/lo[n][rr][h][v]
// ---------------------------------------------------------------------------
__global__ __launch_bounds__(256) void kernT() {
    const int n = blockIdx.x, rr = blockIdx.y;
    __shared__ float tile[VD][HD + 1];
    const float* src = g_A + (size_t)(n * RD + rr) * VD * HD;
    for (int idx = threadIdx.x; idx < VD * HD; idx += 256) {
        int v = idx >> 7, h = idx & 127;
        tile[v][h] = src[idx];
    }
    __syncthreads();
    const size_t obase = (size_t)(n * RD + rr) * HD * VD;
    for (int idx = threadIdx.x; idx < HD * VD; idx += 256) {
        int h = idx >> 6, v = idx & 63;
        unsigned short hi, lo;
        splitf(tile[v][h], hi, lo);
        g_ahi[obase + idx] = hi;
        g_alo[obase + idx] = lo;
    }
}

// ---------------------------------------------------------------------------
// kernVs: elementwise split of v into g_vhi/lo
// ---------------------------------------------------------------------------
__global__ __launch_bounds__(256) void kernVs(const float* __restrict__ v) {
    for (int i = blockIdx.x * 256 + threadIdx.x; i < NB * IJ * VD; i += gridDim.x * 256) {
        unsigned short hi, lo;
        splitf(v[i], hi, lo);
        g_vhi[i] = hi;
        g_vlo[i] = lo;
    }
}

// ---------------------------------------------------------------------------
// kernWs: w2[x][rr][h] -> g_w2hi/lo[rr][x][h]
// ---------------------------------------------------------------------------
__global__ __launch_bounds__(128) void kernWs(const float* __restrict__ w2) {
    const int rr = blockIdx.x, h = threadIdx.x;
    for (int x = 0; x < XD; x++) {
        unsigned short hi, lo;
        splitf(w2[(x * RD + rr) * HD + h], hi, lo);
        g_w2hi[(rr * XD + x) * HD + h] = hi;
        g_w2lo[(rr * XD + x) * HD + h] = lo;
    }
}

// ---------------------------------------------------------------------------
// kernB: per (token tile, n, hblk, rr-half): 32 x { s1 mma, relu*r split, s2 mma }.
// Stage-2 accumulates in registers across all rr; one atomic epilogue.
// ---------------------------------------------------------------------------
extern __shared__ unsigned char smemB[];

__global__ __launch_bounds__(128) void kernB(float* __restrict__ out) {
    const uint32_t sb = smem_u32(smemB);
    const int tid = threadIdx.x, lane = tid & 31, w = tid >> 5;
    const int tile = blockIdx.x, n = blockIdx.y, z = blockIdx.z;
    const int token0 = tile * TM;
    const int h0g = (z & 1) * HC;
    const int rr0 = (z >> 1) * RRG;
    const int m0 = w * 16;

    // V tile fill (once): 64 rows x 128B, padded to 144B stride
    {
        const uint4* s1 = (const uint4*)(g_vhi + (size_t)(n * IJ + token0) * VD);
        const uint4* s2 = (const uint4*)(g_vlo + (size_t)(n * IJ + token0) * VD);
#pragma unroll
        for (int i = tid; i < 512; i += 128) {
            int row = i >> 3, c = i & 7;
            *(uint4*)(smemB + SOFF_VHI + row * ROWB + c * 16) = s1[i];
            *(uint4*)(smemB + SOFF_VLO + row * ROWB + c * 16) = s2[i];
        }
    }

    float oc[8][4];
#pragma unroll
    for (int t = 0; t < 8; t++)
#pragma unroll
        for (int j = 0; j < 4; j++) oc[t][j] = 0.f;

    const int mrow = (lane >> 2);            // 0..7

    for (int rl = 0; rl < RRG; rl++) {
        const int rr = rr0 + rl;
        __syncthreads();   // prev iter stage-2 done reading W tiles

        // fill A-tensor slice [64h][64v] hi/lo
        {
            const uint4* s1 = (const uint4*)(g_ahi + ((size_t)(n * RD + rr) * HD + h0g) * VD);
            const uint4* s2 = (const uint4*)(g_alo + ((size_t)(n * RD + rr) * HD + h0g) * VD);
#pragma unroll
            for (int i = tid; i < 512; i += 128) {
                int row = i >> 3, c = i & 7;
                *(uint4*)(smemB + SOFF_AHI + row * ROWB + c * 16) = s1[i];
                *(uint4*)(smemB + SOFF_ALO + row * ROWB + c * 16) = s2[i];
            }
        }
        // fill w2 slice [64x][64h] hi/lo
        {
#pragma unroll
            for (int i = tid; i < 512; i += 128) {
                int row = i >> 3, c = i & 7;
                const uint4* s1 = (const uint4*)(g_w2hi + (size_t)(rr * XD + row) * HD + h0g);
                const uint4* s2 = (const uint4*)(g_w2lo + (size_t)(rr * XD + row) * HD + h0g);
                *(uint4*)(smemB + SOFF_WHI + row * ROWB + c * 16) = s1[c];
                *(uint4*)(smemB + SOFF_WLO + row * ROWB + c * 16) = s2[c];
            }
        }
        // r scales for this rr (hide latency under the fills/sync)
        const float rsc0 = g_rT[(n * RD + rr) * IJ + token0 + m0 + mrow];
        const float rsc8 = g_rT[(n * RD + rr) * IJ + token0 + m0 + mrow + 8];
        __syncthreads();

        // ---- stage 1: P[16m x 64h] per warp, 3-term split ----
        float pc[8][4];
#pragma unroll
        for (int t = 0; t < 8; t++)
#pragma unroll
            for (int j = 0; j < 4; j++) pc[t][j] = 0.f;

        gemm64(pc, sb + SOFF_VHI, sb + SOFF_AHI, m0, lane);
        gemm64(pc, sb + SOFF_VLO, sb + SOFF_AHI, m0, lane);
        gemm64(pc, sb + SOFF_VHI, sb + SOFF_ALO, m0, lane);

        // ---- epilogue: relu * r, split, store P hi/lo tiles ----
        {
            const uint32_t prow0 = (uint32_t)(m0 + mrow) * ROWB;
            const uint32_t prow8 = prow0 + 8 * ROWB;
#pragma unroll
            for (int nt = 0; nt < 8; nt++) {
                const uint32_t hoff = (uint32_t)(nt * 8 + 2 * (lane & 3)) * 2;
                uint32_t hp, lp;
                split2(fmaxf(pc[nt][0], 0.f) * rsc0, fmaxf(pc[nt][1], 0.f) * rsc0, hp, lp);
                *(uint32_t*)(smemB + SOFF_PHI + prow0 + hoff) = hp;
                *(uint32_t*)(smemB + SOFF_PLO + prow0 + hoff) = lp;
                split2(fmaxf(pc[nt][2], 0.f) * rsc8, fmaxf(pc[nt][3], 0.f) * rsc8, hp, lp);
                *(uint32_t*)(smemB + SOFF_PHI + prow8 + hoff) = hp;
                *(uint32_t*)(smemB + SOFF_PLO + prow8 + hoff) = lp;
            }
        }
        __syncwarp();   // stage-2 A-frags read only this warp's P rows

        // ---- stage 2: OUT[16m x 64x] += P * W2^T, 3-term split ----
        gemm64(oc, sb + SOFF_PHI, sb + SOFF_WHI, m0, lane);
        gemm64(oc, sb + SOFF_PLO, sb + SOFF_WHI, m0, lane);
        gemm64(oc, sb + SOFF_PHI, sb + SOFF_WLO, m0, lane);
    }

    // final epilogue: 4 partial CTAs per out element (2 hblk x 2 rr-halves)
    {
        float* op = out + (size_t)(n * IJ + token0 + m0 + mrow) * XD;
#pragma unroll
        for (int nt = 0; nt < 8; nt++) {
            const int x = nt * 8 + 2 * (lane & 3);
            atomicAdd(op + x,     oc[nt][0]);
            atomicAdd(op + x + 1, oc[nt][1]);
            atomicAdd(op + 8 * XD + x,     oc[nt][2]);
            atomicAdd(op + 8 * XD + x + 1, oc[nt][3]);
        }
    }
}

// ---------------------------------------------------------------------------
extern "C" void kernel_launch(void* const* d_in, const int* in_sizes, int n_in,
                              void* d_out, int out_size) {
    const float* r  = (const float*)d_in[0];
    const float* u  = (const float*)d_in[1];
    const float* v  = (const float*)d_in[2];
    const float* w1 = (const float*)d_in[3];
    const float* w2 = (const float*)d_in[4];
    float* out = (float*)d_out;
    (void)in_sizes; (void)n_in; (void)out_size;

    static int attr_done = 0;
    if (!attr_done) {
        cudaFuncSetAttribute(kernB, cudaFuncAttributeMaxDynamicSharedMemorySize, SMEM_TOTAL);
        attr_done = 1;
    }

    kernR<<<dim3(NB, RD), 256>>>(r);
    kernA<<<dim3(RD, VD), 128>>>(u, w1, out);
    kernT<<<dim3(NB, RD), 256>>>();
    kernVs<<<512, 256>>>(v);
    kernWs<<<RD, 128>>>(w2);
    kernB<<<dim3(IJ / TM, NB, 4), 128, SMEM_TOTAL>>>(out);
}

// round 8
// speedup vs baseline: 2.3490x; 1.0906x over previous
#include <cuda_runtime.h>
#include <cuda_bf16.h>
#include <cstdint>

#define RD 64
#define UD 64
#define VD 64
#define HD 128
#define XD 64
#define NB 8
#define IJ 1024
#define TM 64            // token tile
#define HC 64            // h per CTA (hblk)
#define RRG 32           // rr per CTA

// smem: 6 bf16 tiles [64 rows][72 cols] (row stride 144B, LDSM conflict-free)
#define ROWB 144
#define TILEB (64 * ROWB)          // 9216
#define SOFF_VHI 0
#define SOFF_VLO (1 * TILEB)
#define SOFF_AHI (2 * TILEB)
#define SOFF_ALO (3 * TILEB)
#define SOFF_WHI (4 * TILEB)
#define SOFF_WLO (5 * TILEB)
#define SMEM_TOTAL (6 * TILEB)     // 55296 -> 4 CTAs/SM

// ---------------- gmem scratch ----------------
__device__ float g_A[NB * RD * VD * HD];                       // fp32 A, 16.8MB
__device__ float g_rT[NB * RD * IJ];                           // r^T, 2MB
__device__ __align__(16) unsigned short g_ahi[NB * RD * HD * VD];  // A split [n][rr][h][v]
__device__ __align__(16) unsigned short g_alo[NB * RD * HD * VD];
__device__ __align__(16) unsigned short g_vhi[NB * IJ * VD];       // V split [n][m][v]
__device__ __align__(16) unsigned short g_vlo[NB * IJ * VD];
__device__ __align__(16) unsigned short g_w2hi[RD * XD * HD];      // w2 split [rr][x][h]
__device__ __align__(16) unsigned short g_w2lo[RD * XD * HD];

// ---------------- helpers ----------------
__device__ __forceinline__ uint32_t smem_u32(const void* p) {
    uint32_t a;
    asm("{ .reg .u64 t; cvta.to.shared.u64 t, %1; cvt.u32.u64 %0, t; }" : "=r"(a) : "l"(p));
    return a;
}
__device__ __forceinline__ void ldsm4(uint32_t& r0, uint32_t& r1, uint32_t& r2, uint32_t& r3,
                                      uint32_t addr) {
    asm volatile("ldmatrix.sync.aligned.m8n8.x4.shared.b16 {%0,%1,%2,%3}, [%4];"
                 : "=r"(r0), "=r"(r1), "=r"(r2), "=r"(r3) : "r"(addr));
}
__device__ __forceinline__ void mma_bf16(float* d, uint32_t a0, uint32_t a1, uint32_t a2,
                                         uint32_t a3, uint32_t b0, uint32_t b1) {
    asm volatile(
        "mma.sync.aligned.m16n8k16.row.col.f32.bf16.bf16.f32 "
        "{%0,%1,%2,%3}, {%4,%5,%6,%7}, {%8,%9}, {%0,%1,%2,%3};"
        : "+f"(d[0]), "+f"(d[1]), "+f"(d[2]), "+f"(d[3])
        : "r"(a0), "r"(a1), "r"(a2), "r"(a3), "r"(b0), "r"(b1));
}
__device__ __forceinline__ void splitf(float x, unsigned short& hi, unsigned short& lo) {
    __nv_bfloat16 h = __float2bfloat16(x);
    __nv_bfloat16 l = __float2bfloat16(x - __bfloat162float(h));
    hi = __bfloat16_as_ushort(h);
    lo = __bfloat16_as_ushort(l);
}
__device__ __forceinline__ void split2(float p0, float p1, uint32_t& hp, uint32_t& lp) {
    unsigned short h0, l0, h1, l1;
    splitf(p0, h0, l0);
    splitf(p1, h1, l1);
    hp = ((uint32_t)h1 << 16) | h0;   // first element in low half (ascending cols)
    lp = ((uint32_t)l1 << 16) | l0;
}

// K=64 GEMM, A from smem via ldsm: acc[8][4] covers 16m x 64n.
__device__ __forceinline__ void gemm64(float acc[8][4], uint32_t abase, uint32_t bbase,
                                       int m0, int lane) {
    const uint32_t aaddr = abase + (uint32_t)(m0 + (lane & 15)) * ROWB
                         + (uint32_t)((lane >> 4) << 3) * 2;
    const uint32_t baddr = bbase + (uint32_t)(((lane >> 4) << 3) + (lane & 7)) * ROWB
                         + (uint32_t)(((lane >> 3) & 1) << 3) * 2;
#pragma unroll
    for (int k0 = 0; k0 < 64; k0 += 16) {
        uint32_t a0, a1, a2, a3;
        ldsm4(a0, a1, a2, a3, aaddr + k0 * 2);
#pragma unroll
        for (int nt = 0; nt < 4; nt++) {
            uint32_t b0, b1, b2, b3;
            ldsm4(b0, b1, b2, b3, baddr + nt * 16 * ROWB + k0 * 2);
            mma_bf16(acc[2 * nt],     a0, a1, a2, a3, b0, b1);
            mma_bf16(acc[2 * nt + 1], a0, a1, a2, a3, b2, b3);
        }
    }
}

// K=64 GEMM, A fragments already in registers (af[kk][0..3]).
__device__ __forceinline__ void gemm64_ra(float acc[8][4], const uint32_t af[4][4],
                                          uint32_t bbase, int lane) {
    const uint32_t baddr = bbase + (uint32_t)(((lane >> 4) << 3) + (lane & 7)) * ROWB
                         + (uint32_t)(((lane >> 3) & 1) << 3) * 2;
#pragma unroll
    for (int kk = 0; kk < 4; kk++) {
#pragma unroll
        for (int nt = 0; nt < 4; nt++) {
            uint32_t b0, b1, b2, b3;
            ldsm4(b0, b1, b2, b3, baddr + nt * 16 * ROWB + kk * 32);
            mma_bf16(acc[2 * nt],     af[kk][0], af[kk][1], af[kk][2], af[kk][3], b0, b1);
            mma_bf16(acc[2 * nt + 1], af[kk][0], af[kk][1], af[kk][2], af[kk][3], b2, b3);
        }
    }
}

// ---------------------------------------------------------------------------
// kernR: g_rT[n][rr][t] = r[n][t][rr]
// ---------------------------------------------------------------------------
__global__ __launch_bounds__(256) void kernR(const float* __restrict__ r) {
    const int n = blockIdx.x, rr = blockIdx.y;
    for (int t = threadIdx.x; t < IJ; t += 256)
        g_rT[(n * RD + rr) * IJ + t] = r[(n * IJ + t) * RD + rr];
}

// ---------------------------------------------------------------------------
// kernA: A[n,rr,v,h] = sum_u w1*u (fp32, g_A); also zeroes the output.
// ---------------------------------------------------------------------------
__global__ __launch_bounds__(128) void kernA(const float* __restrict__ u,
                                             const float* __restrict__ w1,
                                             float* __restrict__ out) {
    const int rr = blockIdx.x, vv = blockIdx.y, h = threadIdx.x;
    out[(blockIdx.y * RD + blockIdx.x) * 128 + threadIdx.x] = 0.f;

    __shared__ float us[NB][UD];
    for (int idx = threadIdx.x; idx < NB * UD; idx += 128) {
        int n = idx >> 6, uu = idx & 63;
        us[n][uu] = u[((n * RD + rr) * UD + uu) * VD + vv];
    }
    __syncthreads();

    float acc[NB];
#pragma unroll
    for (int n = 0; n < NB; n++) acc[n] = 0.f;
    const float* w1p = w1 + (rr * UD * VD + vv) * HD + h;
#pragma unroll 4
    for (int uu = 0; uu < UD; uu++) {
        float w = w1p[uu * (VD * HD)];
#pragma unroll
        for (int n = 0; n < NB; n++) acc[n] = fmaf(w, us[n][uu], acc[n]);
    }
#pragma unroll
    for (int n = 0; n < NB; n++)
        g_A[((n * RD + rr) * VD + vv) * HD + h] = acc[n];
}

// ---------------------------------------------------------------------------
// kernT: transpose + split g_A[n][rr][v][h] -> g_ahi/lo[n][rr][h][v]
// ---------------------------------------------------------------------------
__global__ __launch_bounds__(256) void kernT() {
    const int n = blockIdx.x, rr = blockIdx.y;
    __shared__ float tile[VD][HD + 1];
    const float* src = g_A + (size_t)(n * RD + rr) * VD * HD;
    for (int idx = threadIdx.x; idx < VD * HD; idx += 256) {
        int v = idx >> 7, h = idx & 127;
        tile[v][h] = src[idx];
    }
    __syncthreads();
    const size_t obase = (size_t)(n * RD + rr) * HD * VD;
    for (int idx = threadIdx.x; idx < HD * VD; idx += 256) {
        int h = idx >> 6, v = idx & 63;
        unsigned short hi, lo;
        splitf(tile[v][h], hi, lo);
        g_ahi[obase + idx] = hi;
        g_alo[obase + idx] = lo;
    }
}

// ---------------------------------------------------------------------------
// kernVs: elementwise split of v into g_vhi/lo
// ---------------------------------------------------------------------------
__global__ __launch_bounds__(256) void kernVs(const float* __restrict__ v) {
    for (int i = blockIdx.x * 256 + threadIdx.x; i < NB * IJ * VD; i += gridDim.x * 256) {
        unsigned short hi, lo;
        splitf(v[i], hi, lo);
        g_vhi[i] = hi;
        g_vlo[i] = lo;
    }
}

// ---------------------------------------------------------------------------
// kernWs: w2[x][rr][h] -> g_w2hi/lo[rr][x][h]
// ---------------------------------------------------------------------------
__global__ __launch_bounds__(128) void kernWs(const float* __restrict__ w2) {
    const int rr = blockIdx.x, h = threadIdx.x;
    for (int x = 0; x < XD; x++) {
        unsigned short hi, lo;
        splitf(w2[(x * RD + rr) * HD + h], hi, lo);
        g_w2hi[(rr * XD + x) * HD + h] = hi;
        g_w2lo[(rr * XD + x) * HD + h] = lo;
    }
}

// ---------------------------------------------------------------------------
// kernB: per (token tile, n, hblk, rr-half): 32 x { s1 mma, reg epilogue, s2 mma }.
// Stage-1 D fragments are re-used register-direct as stage-2 A fragments
// (identical lane/row/col layout), so P never touches smem.
// ---------------------------------------------------------------------------
extern __shared__ unsigned char smemB[];

__global__ __launch_bounds__(128, 4) void kernB(float* __restrict__ out) {
    const uint32_t sb = smem_u32(smemB);
    const int tid = threadIdx.x, lane = tid & 31, w = tid >> 5;
    const int tile = blockIdx.x, n = blockIdx.y, z = blockIdx.z;
    const int token0 = tile * TM;
    const int h0g = (z & 1) * HC;
    const int rr0 = (z >> 1) * RRG;
    const int m0 = w * 16;
    const int mrow = lane >> 2;              // 0..7

    // V tile fill (once): 64 rows x 128B, 144B stride
    {
        const uint4* s1 = (const uint4*)(g_vhi + (size_t)(n * IJ + token0) * VD);
        const uint4* s2 = (const uint4*)(g_vlo + (size_t)(n * IJ + token0) * VD);
#pragma unroll
        for (int i = tid; i < 512; i += 128) {
            int row = i >> 3, c = i & 7;
            *(uint4*)(smemB + SOFF_VHI + row * ROWB + c * 16) = s1[i];
            *(uint4*)(smemB + SOFF_VLO + row * ROWB + c * 16) = s2[i];
        }
    }

    float oc[8][4];
#pragma unroll
    for (int t = 0; t < 8; t++)
#pragma unroll
        for (int j = 0; j < 4; j++) oc[t][j] = 0.f;

    for (int rl = 0; rl < RRG; rl++) {
        const int rr = rr0 + rl;
        __syncthreads();   // prev iter stage-2 done reading A/W tiles

        // fill A-tensor slice [64h][64v] hi/lo
        {
            const uint4* s1 = (const uint4*)(g_ahi + ((size_t)(n * RD + rr) * HD + h0g) * VD);
            const uint4* s2 = (const uint4*)(g_alo + ((size_t)(n * RD + rr) * HD + h0g) * VD);
#pragma unroll
            for (int i = tid; i < 512; i += 128) {
                int row = i >> 3, c = i & 7;
                *(uint4*)(smemB + SOFF_AHI + row * ROWB + c * 16) = s1[i];
                *(uint4*)(smemB + SOFF_ALO + row * ROWB + c * 16) = s2[i];
            }
        }
        // fill w2 slice [64x][64h] hi/lo
        {
#pragma unroll
            for (int i = tid; i < 512; i += 128) {
                int row = i >> 3, c = i & 7;
                const uint4* s1 = (const uint4*)(g_w2hi + (size_t)(rr * XD + row) * HD + h0g);
                const uint4* s2 = (const uint4*)(g_w2lo + (size_t)(rr * XD + row) * HD + h0g);
                *(uint4*)(smemB + SOFF_WHI + row * ROWB + c * 16) = s1[c];
                *(uint4*)(smemB + SOFF_WLO + row * ROWB + c * 16) = s2[c];
            }
        }
        const float rsc0 = g_rT[(n * RD + rr) * IJ + token0 + m0 + mrow];
        const float rsc8 = g_rT[(n * RD + rr) * IJ + token0 + m0 + mrow + 8];
        __syncthreads();

        // ---- stage 1: P[16m x 64h] per warp, 3-term split ----
        float pc[8][4];
#pragma unroll
        for (int t = 0; t < 8; t++)
#pragma unroll
            for (int j = 0; j < 4; j++) pc[t][j] = 0.f;

        gemm64(pc, sb + SOFF_VHI, sb + SOFF_AHI, m0, lane);
        gemm64(pc, sb + SOFF_VLO, sb + SOFF_AHI, m0, lane);
        gemm64(pc, sb + SOFF_VHI, sb + SOFF_ALO, m0, lane);

        // ---- epilogue in registers: relu * r, split -> stage-2 A fragments ----
        // D(nt)[d0,d1,d2,d3] -> A(kk): a0=pack(d0,d1)|nt=2kk, a1=pack(d2,d3)|nt=2kk,
        //                              a2=pack(d0,d1)|nt=2kk+1, a3=pack(d2,d3)|nt=2kk+1
        uint32_t phi[4][4], plo[4][4];
#pragma unroll
        for (int kk = 0; kk < 4; kk++) {
            split2(fmaxf(pc[2 * kk][0], 0.f) * rsc0, fmaxf(pc[2 * kk][1], 0.f) * rsc0,
                   phi[kk][0], plo[kk][0]);
            split2(fmaxf(pc[2 * kk][2], 0.f) * rsc8, fmaxf(pc[2 * kk][3], 0.f) * rsc8,
                   phi[kk][1], plo[kk][1]);
            split2(fmaxf(pc[2 * kk + 1][0], 0.f) * rsc0, fmaxf(pc[2 * kk + 1][1], 0.f) * rsc0,
                   phi[kk][2], plo[kk][2]);
            split2(fmaxf(pc[2 * kk + 1][2], 0.f) * rsc8, fmaxf(pc[2 * kk + 1][3], 0.f) * rsc8,
                   phi[kk][3], plo[kk][3]);
        }

        // ---- stage 2: OUT[16m x 64x] += P * W2^T, 3-term split ----
        gemm64_ra(oc, phi, sb + SOFF_WHI, lane);
        gemm64_ra(oc, plo, sb + SOFF_WHI, lane);
        gemm64_ra(oc, phi, sb + SOFF_WLO, lane);
    }

    // final epilogue: 4 partial CTAs per out element (2 hblk x 2 rr-halves)
    {
        float* op = out + (size_t)(n * IJ + token0 + m0 + mrow) * XD;
#pragma unroll
        for (int nt = 0; nt < 8; nt++) {
            const int x = nt * 8 + 2 * (lane & 3);
            atomicAdd(op + x,     oc[nt][0]);
            atomicAdd(op + x + 1, oc[nt][1]);
            atomicAdd(op + 8 * XD + x,     oc[nt][2]);
            atomicAdd(op + 8 * XD + x + 1, oc[nt][3]);
        }
    }
}

// ---------------------------------------------------------------------------
extern "C" void kernel_launch(void* const* d_in, const int* in_sizes, int n_in,
                              void* d_out, int out_size) {
    const float* r  = (const float*)d_in[0];
    const float* u  = (const float*)d_in[1];
    const float* v  = (const float*)d_in[2];
    const float* w1 = (const float*)d_in[3];
    const float* w2 = (const float*)d_in[4];
    float* out = (float*)d_out;
    (void)in_sizes; (void)n_in; (void)out_size;

    static int attr_done = 0;
    if (!attr_done) {
        cudaFuncSetAttribute(kernB, cudaFuncAttributeMaxDynamicSharedMemorySize, SMEM_TOTAL);
        attr_done = 1;
    }

    kernR<<<dim3(NB, RD), 256>>>(r);
    kernA<<<dim3(RD, VD), 128>>>(u, w1, out);
    kernT<<<dim3(NB, RD), 256>>>();
    kernVs<<<512, 256>>>(v);
    kernWs<<<RD, 128>>>(w2);
    kernB<<<dim3(IJ / TM, NB, 4), 128, SMEM_TOTAL>>>(out);
}

// round 9
// speedup vs baseline: 2.5437x; 1.0829x over previous
#include <cuda_runtime.h>
#include <cuda_bf16.h>
#include <cstdint>

#define RD 64
#define UD 64
#define VD 64
#define HD 128
#define XD 64
#define NB 8
#define IJ 1024
#define TM 128           // token tile
#define HC 64            // h per CTA (hblk)
#define RRG 32           // rr per CTA

// smem: V tiles (128 rows) + double-buffered A/W tiles (64 rows), 144B row stride
#define ROWB 144
#define VTILEB (128 * ROWB)        // 18432
#define TILEB  (64 * ROWB)         // 9216
#define SOFF_VHI 0
#define SOFF_VLO VTILEB
#define SOFF_BUF (2 * VTILEB)      // two buffers of 4 tiles each
#define BUFB (4 * TILEB)           // 36864: [AHI][ALO][WHI][WLO]
#define SMEM_TOTAL (2 * VTILEB + 2 * BUFB)   // 110592 -> 2 CTAs/SM

// ---------------- gmem scratch ----------------
__device__ float g_A[NB * RD * VD * HD];                       // fp32 A, 16.8MB
__device__ float g_rT[NB * RD * IJ];                           // r^T, 2MB
__device__ __align__(16) unsigned short g_ahi[NB * RD * HD * VD];  // A split [n][rr][h][v]
__device__ __align__(16) unsigned short g_alo[NB * RD * HD * VD];
__device__ __align__(16) unsigned short g_vhi[NB * IJ * VD];       // V split [n][m][v]
__device__ __align__(16) unsigned short g_vlo[NB * IJ * VD];
__device__ __align__(16) unsigned short g_w2hi[RD * XD * HD];      // w2 split [rr][x][h]
__device__ __align__(16) unsigned short g_w2lo[RD * XD * HD];

// ---------------- helpers ----------------
__device__ __forceinline__ uint32_t smem_u32(const void* p) {
    uint32_t a;
    asm("{ .reg .u64 t; cvta.to.shared.u64 t, %1; cvt.u32.u64 %0, t; }" : "=r"(a) : "l"(p));
    return a;
}
__device__ __forceinline__ void cp16(uint32_t dst, const void* src) {
    asm volatile("cp.async.cg.shared.global [%0], [%1], 16;" :: "r"(dst), "l"(src));
}
#define CP_COMMIT() asm volatile("cp.async.commit_group;" ::: "memory")
#define CP_WAIT1()  asm volatile("cp.async.wait_group 1;" ::: "memory")
#define CP_WAIT0()  asm volatile("cp.async.wait_group 0;" ::: "memory")

__device__ __forceinline__ void ldsm4(uint32_t& r0, uint32_t& r1, uint32_t& r2, uint32_t& r3,
                                      uint32_t addr) {
    asm volatile("ldmatrix.sync.aligned.m8n8.x4.shared.b16 {%0,%1,%2,%3}, [%4];"
                 : "=r"(r0), "=r"(r1), "=r"(r2), "=r"(r3) : "r"(addr));
}
__device__ __forceinline__ void mma_bf16(float* d, uint32_t a0, uint32_t a1, uint32_t a2,
                                         uint32_t a3, uint32_t b0, uint32_t b1) {
    asm volatile(
        "mma.sync.aligned.m16n8k16.row.col.f32.bf16.bf16.f32 "
        "{%0,%1,%2,%3}, {%4,%5,%6,%7}, {%8,%9}, {%0,%1,%2,%3};"
        : "+f"(d[0]), "+f"(d[1]), "+f"(d[2]), "+f"(d[3])
        : "r"(a0), "r"(a1), "r"(a2), "r"(a3), "r"(b0), "r"(b1));
}
__device__ __forceinline__ void splitf(float x, unsigned short& hi, unsigned short& lo) {
    __nv_bfloat16 h = __float2bfloat16(x);
    __nv_bfloat16 l = __float2bfloat16(x - __bfloat162float(h));
    hi = __bfloat16_as_ushort(h);
    lo = __bfloat16_as_ushort(l);
}
__device__ __forceinline__ void split2(float p0, float p1, uint32_t& hp, uint32_t& lp) {
    unsigned short h0, l0, h1, l1;
    splitf(p0, h0, l0);
    splitf(p1, h1, l1);
    hp = ((uint32_t)h1 << 16) | h0;
    lp = ((uint32_t)l1 << 16) | l0;
}

// K=64 GEMM, A from smem via ldsm: acc[8][4] covers 16m x 64n.
__device__ __forceinline__ void gemm64(float acc[8][4], uint32_t abase, uint32_t bbase,
                                       int m0, int lane) {
    const uint32_t aaddr = abase + (uint32_t)(m0 + (lane & 15)) * ROWB
                         + (uint32_t)((lane >> 4) << 3) * 2;
    const uint32_t baddr = bbase + (uint32_t)(((lane >> 4) << 3) + (lane & 7)) * ROWB
                         + (uint32_t)(((lane >> 3) & 1) << 3) * 2;
#pragma unroll
    for (int k0 = 0; k0 < 64; k0 += 16) {
        uint32_t a0, a1, a2, a3;
        ldsm4(a0, a1, a2, a3, aaddr + k0 * 2);
#pragma unroll
        for (int nt = 0; nt < 4; nt++) {
            uint32_t b0, b1, b2, b3;
            ldsm4(b0, b1, b2, b3, baddr + nt * 16 * ROWB + k0 * 2);
            mma_bf16(acc[2 * nt],     a0, a1, a2, a3, b0, b1);
            mma_bf16(acc[2 * nt + 1], a0, a1, a2, a3, b2, b3);
        }
    }
}

// K=64 GEMM, A fragments already in registers.
__device__ __forceinline__ void gemm64_ra(float acc[8][4], const uint32_t af[4][4],
                                          uint32_t bbase, int lane) {
    const uint32_t baddr = bbase + (uint32_t)(((lane >> 4) << 3) + (lane & 7)) * ROWB
                         + (uint32_t)(((lane >> 3) & 1) << 3) * 2;
#pragma unroll
    for (int kk = 0; kk < 4; kk++) {
#pragma unroll
        for (int nt = 0; nt < 4; nt++) {
            uint32_t b0, b1, b2, b3;
            ldsm4(b0, b1, b2, b3, baddr + nt * 16 * ROWB + kk * 32);
            mma_bf16(acc[2 * nt],     af[kk][0], af[kk][1], af[kk][2], af[kk][3], b0, b1);
            mma_bf16(acc[2 * nt + 1], af[kk][0], af[kk][1], af[kk][2], af[kk][3], b2, b3);
        }
    }
}

// ---------------------------------------------------------------------------
// kernR / kernA / kernT / kernVs / kernWs: precompute (unchanged from R8)
// ---------------------------------------------------------------------------
__global__ __launch_bounds__(256) void kernR(const float* __restrict__ r) {
    const int n = blockIdx.x, rr = blockIdx.y;
    for (int t = threadIdx.x; t < IJ; t += 256)
        g_rT[(n * RD + rr) * IJ + t] = r[(n * IJ + t) * RD + rr];
}

__global__ __launch_bounds__(128) void kernA(const float* __restrict__ u,
                                             const float* __restrict__ w1,
                                             float* __restrict__ out) {
    const int rr = blockIdx.x, vv = blockIdx.y, h = threadIdx.x;
    out[(blockIdx.y * RD + blockIdx.x) * 128 + threadIdx.x] = 0.f;

    __shared__ float us[NB][UD];
    for (int idx = threadIdx.x; idx < NB * UD; idx += 128) {
        int n = idx >> 6, uu = idx & 63;
        us[n][uu] = u[((n * RD + rr) * UD + uu) * VD + vv];
    }
    __syncthreads();

    float acc[NB];
#pragma unroll
    for (int n = 0; n < NB; n++) acc[n] = 0.f;
    const float* w1p = w1 + (rr * UD * VD + vv) * HD + h;
#pragma unroll 4
    for (int uu = 0; uu < UD; uu++) {
        float w = w1p[uu * (VD * HD)];
#pragma unroll
        for (int n = 0; n < NB; n++) acc[n] = fmaf(w, us[n][uu], acc[n]);
    }
#pragma unroll
    for (int n = 0; n < NB; n++)
        g_A[((n * RD + rr) * VD + vv) * HD + h] = acc[n];
}

__global__ __launch_bounds__(256) void kernT() {
    const int n = blockIdx.x, rr = blockIdx.y;
    __shared__ float tile[VD][HD + 1];
    const float* src = g_A + (size_t)(n * RD + rr) * VD * HD;
    for (int idx = threadIdx.x; idx < VD * HD; idx += 256) {
        int v = idx >> 7, h = idx & 127;
        tile[v][h] = src[idx];
    }
    __syncthreads();
    const size_t obase = (size_t)(n * RD + rr) * HD * VD;
    for (int idx = threadIdx.x; idx < HD * VD; idx += 256) {
        int h = idx >> 6, v = idx & 63;
        unsigned short hi, lo;
        splitf(tile[v][h], hi, lo);
        g_ahi[obase + idx] = hi;
        g_alo[obase + idx] = lo;
    }
}

__global__ __launch_bounds__(256) void kernVs(const float* __restrict__ v) {
    for (int i = blockIdx.x * 256 + threadIdx.x; i < NB * IJ * VD; i += gridDim.x * 256) {
        unsigned short hi, lo;
        splitf(v[i], hi, lo);
        g_vhi[i] = hi;
        g_vlo[i] = lo;
    }
}

__global__ __launch_bounds__(128) void kernWs(const float* __restrict__ w2) {
    const int rr = blockIdx.x, h = threadIdx.x;
    for (int x = 0; x < XD; x++) {
        unsigned short hi, lo;
        splitf(w2[(x * RD + rr) * HD + h], hi, lo);
        g_w2hi[(rr * XD + x) * HD + h] = hi;
        g_w2lo[(rr * XD + x) * HD + h] = lo;
    }
}

// ---------------------------------------------------------------------------
// kernB: 256 thr, tile 128m x 64c, cp.async double-buffered A/W tiles.
// grid (8 token tiles, 8 n, 2 hblk x 2 rr-halves) = 256 CTAs, 2 CTAs/SM.
// ---------------------------------------------------------------------------
extern __shared__ unsigned char smemB[];

// issue cp.async fills of one buffer (A hi/lo + W hi/lo) for a given (n, rr, h0g)
__device__ __forceinline__ void issue_fills(uint32_t sbuf, int n, int rr, int h0g, int tid) {
    const unsigned short* a1 = g_ahi + ((size_t)(n * RD + rr) * HD + h0g) * VD;
    const unsigned short* a2 = g_alo + ((size_t)(n * RD + rr) * HD + h0g) * VD;
#pragma unroll
    for (int j = 0; j < 2; j++) {
        int i = tid + j * 256;               // 0..511
        int row = i >> 3, c = i & 7;
        uint32_t dst = sbuf + row * ROWB + c * 16;
        cp16(dst,             a1 + i * 8);
        cp16(dst + TILEB,     a2 + i * 8);
        const unsigned short* w1p = g_w2hi + (size_t)(rr * XD + row) * HD + h0g + c * 8;
        const unsigned short* w2p = g_w2lo + (size_t)(rr * XD + row) * HD + h0g + c * 8;
        cp16(dst + 2 * TILEB, w1p);
        cp16(dst + 3 * TILEB, w2p);
    }
}

__global__ __launch_bounds__(256, 2) void kernB(float* __restrict__ out) {
    const uint32_t sb = smem_u32(smemB);
    const int tid = threadIdx.x, lane = tid & 31, w = tid >> 5;
    const int tile = blockIdx.x, n = blockIdx.y, z = blockIdx.z;
    const int token0 = tile * TM;
    const int h0g = (z & 1) * HC;
    const int rr0 = (z >> 1) * RRG;
    const int m0 = w * 16;
    const int mrow = lane >> 2;              // 0..7

    // V tile fill (once): 128 rows x 128B, 144B stride
    {
        const uint4* s1 = (const uint4*)(g_vhi + (size_t)(n * IJ + token0) * VD);
        const uint4* s2 = (const uint4*)(g_vlo + (size_t)(n * IJ + token0) * VD);
#pragma unroll
        for (int j = 0; j < 4; j++) {
            int i = tid + j * 256;           // 0..1023
            int row = i >> 3, c = i & 7;
            *(uint4*)(smemB + SOFF_VHI + row * ROWB + c * 16) = s1[i];
            *(uint4*)(smemB + SOFF_VLO + row * ROWB + c * 16) = s2[i];
        }
    }
    // prefetch rr0 into buffer 0
    issue_fills(sb + SOFF_BUF, n, rr0, h0g, tid);
    CP_COMMIT();

    float oc[8][4];
#pragma unroll
    for (int t = 0; t < 8; t++)
#pragma unroll
        for (int j = 0; j < 4; j++) oc[t][j] = 0.f;

    for (int rl = 0; rl < RRG; rl++) {
        const int rr = rr0 + rl;
        const uint32_t sbuf = sb + SOFF_BUF + (rl & 1) * BUFB;
        const uint32_t snxt = sb + SOFF_BUF + ((rl & 1) ^ 1) * BUFB;

        __syncthreads();   // prev iter compute done (next buffer free for overwrite)
        if (rl + 1 < RRG) {
            issue_fills(snxt, n, rr + 1, h0g, tid);
            CP_COMMIT();
            CP_WAIT1();    // current buffer's group complete
        } else {
            CP_WAIT0();
        }
        const float rsc0 = g_rT[(n * RD + rr) * IJ + token0 + m0 + mrow];
        const float rsc8 = g_rT[(n * RD + rr) * IJ + token0 + m0 + mrow + 8];
        __syncthreads();   // current buffer (and V on rl=0) visible to all warps

        // ---- stage 1: P[16m x 64h] per warp, 3-term split ----
        float pc[8][4];
#pragma unroll
        for (int t = 0; t < 8; t++)
#pragma unroll
            for (int j = 0; j < 4; j++) pc[t][j] = 0.f;

        gemm64(pc, sb + SOFF_VHI, sbuf,          m0, lane);   // Vhi * Ahi
        gemm64(pc, sb + SOFF_VLO, sbuf,          m0, lane);   // Vlo * Ahi
        gemm64(pc, sb + SOFF_VHI, sbuf + TILEB,  m0, lane);   // Vhi * Alo

        // ---- epilogue in registers: relu * r, split -> stage-2 A fragments ----
        uint32_t phi[4][4], plo[4][4];
#pragma unroll
        for (int kk = 0; kk < 4; kk++) {
            split2(fmaxf(pc[2 * kk][0], 0.f) * rsc0, fmaxf(pc[2 * kk][1], 0.f) * rsc0,
                   phi[kk][0], plo[kk][0]);
            split2(fmaxf(pc[2 * kk][2], 0.f) * rsc8, fmaxf(pc[2 * kk][3], 0.f) * rsc8,
                   phi[kk][1], plo[kk][1]);
            split2(fmaxf(pc[2 * kk + 1][0], 0.f) * rsc0, fmaxf(pc[2 * kk + 1][1], 0.f) * rsc0,
                   phi[kk][2], plo[kk][2]);
            split2(fmaxf(pc[2 * kk + 1][2], 0.f) * rsc8, fmaxf(pc[2 * kk + 1][3], 0.f) * rsc8,
                   phi[kk][3], plo[kk][3]);
        }

        // ---- stage 2: OUT[16m x 64x] += P * W2^T, 3-term split ----
        gemm64_ra(oc, phi, sbuf + 2 * TILEB, lane);           // Phi * Whi
        gemm64_ra(oc, plo, sbuf + 2 * TILEB, lane);           // Plo * Whi
        gemm64_ra(oc, phi, sbuf + 3 * TILEB, lane);           // Phi * Wlo
    }

    // final epilogue: 4 partial CTAs per out element (2 hblk x 2 rr-halves)
    {
        float* op = out + (size_t)(n * IJ + token0 + m0 + mrow) * XD;
#pragma unroll
        for (int nt = 0; nt < 8; nt++) {
            const int x = nt * 8 + 2 * (lane & 3);
            atomicAdd(op + x,     oc[nt][0]);
            atomicAdd(op + x + 1, oc[nt][1]);
            atomicAdd(op + 8 * XD + x,     oc[nt][2]);
            atomicAdd(op + 8 * XD + x + 1, oc[nt][3]);
        }
    }
}

// ---------------------------------------------------------------------------
extern "C" void kernel_launch(void* const* d_in, const int* in_sizes, int n_in,
                              void* d_out, int out_size) {
    const float* r  = (const float*)d_in[0];
    const float* u  = (const float*)d_in[1];
    const float* v  = (const float*)d_in[2];
    const float* w1 = (const float*)d_in[3];
    const float* w2 = (const float*)d_in[4];
    float* out = (float*)d_out;
    (void)in_sizes; (void)n_in; (void)out_size;

    static int attr_done = 0;
    if (!attr_done) {
        cudaFuncSetAttribute(kernB, cudaFuncAttributeMaxDynamicSharedMemorySize, SMEM_TOTAL);
        attr_done = 1;
    }

    kernR<<<dim3(NB, RD), 256>>>(r);
    kernA<<<dim3(RD, VD), 128>>>(u, w1, out);
    kernT<<<dim3(NB, RD), 256>>>();
    kernVs<<<512, 256>>>(v);
    kernWs<<<RD, 128>>>(w2);
    kernB<<<dim3(IJ / TM, NB, 4), 256, SMEM_TOTAL>>>(out);
}

// round 10
// speedup vs baseline: 2.8585x; 1.1238x over previous
#include <cuda_runtime.h>
#include <cuda_bf16.h>
#include <cstdint>

#define RD 64
#define UD 64
#define VD 64
#define HD 128
#define XD 64
#define NB 8
#define IJ 1024
#define TM 128           // token tile
#define HC 64            // h per CTA (hblk)
#define RRG 32           // rr per CTA

// smem: V tiles (128 rows) + double-buffered A/W tiles (64 rows), 144B row stride
#define ROWB 144
#define VTILEB (128 * ROWB)        // 18432
#define TILEB  (64 * ROWB)         // 9216
#define SOFF_VHI 0
#define SOFF_VLO VTILEB
#define SOFF_BUF (2 * VTILEB)      // two buffers of 4 tiles each
#define BUFB (4 * TILEB)           // 36864: [AHI][ALO][WHI][WLO]
#define SMEM_TOTAL (2 * VTILEB + 2 * BUFB)   // 110592 -> 2 CTAs/SM

// ---------------- gmem scratch ----------------
__device__ float g_A[NB * RD * VD * HD];                       // fp32 A, 16.8MB
__device__ float g_rT[NB * RD * IJ];                           // r^T, 2MB
__device__ __align__(16) unsigned short g_ahi[NB * RD * HD * VD];  // A split [n][rr][h][v]
__device__ __align__(16) unsigned short g_alo[NB * RD * HD * VD];
__device__ __align__(16) unsigned short g_vhi[NB * IJ * VD];       // V split [n][m][v]
__device__ __align__(16) unsigned short g_vlo[NB * IJ * VD];
__device__ __align__(16) unsigned short g_w2hi[RD * XD * HD];      // w2 split [rr][x][h]
__device__ __align__(16) unsigned short g_w2lo[RD * XD * HD];

// ---------------- helpers ----------------
__device__ __forceinline__ uint32_t smem_u32(const void* p) {
    uint32_t a;
    asm("{ .reg .u64 t; cvta.to.shared.u64 t, %1; cvt.u32.u64 %0, t; }" : "=r"(a) : "l"(p));
    return a;
}
__device__ __forceinline__ void cp16(uint32_t dst, const void* src) {
    asm volatile("cp.async.cg.shared.global [%0], [%1], 16;" :: "r"(dst), "l"(src));
}
#define CP_COMMIT() asm volatile("cp.async.commit_group;" ::: "memory")
#define CP_WAIT1()  asm volatile("cp.async.wait_group 1;" ::: "memory")
#define CP_WAIT0()  asm volatile("cp.async.wait_group 0;" ::: "memory")

__device__ __forceinline__ void ldsm4(uint32_t& r0, uint32_t& r1, uint32_t& r2, uint32_t& r3,
                                      uint32_t addr) {
    asm volatile("ldmatrix.sync.aligned.m8n8.x4.shared.b16 {%0,%1,%2,%3}, [%4];"
                 : "=r"(r0), "=r"(r1), "=r"(r2), "=r"(r3) : "r"(addr));
}
__device__ __forceinline__ void mma_bf16(float* d, uint32_t a0, uint32_t a1, uint32_t a2,
                                         uint32_t a3, uint32_t b0, uint32_t b1) {
    asm volatile(
        "mma.sync.aligned.m16n8k16.row.col.f32.bf16.bf16.f32 "
        "{%0,%1,%2,%3}, {%4,%5,%6,%7}, {%8,%9}, {%0,%1,%2,%3};"
        : "+f"(d[0]), "+f"(d[1]), "+f"(d[2]), "+f"(d[3])
        : "r"(a0), "r"(a1), "r"(a2), "r"(a3), "r"(b0), "r"(b1));
}
__device__ __forceinline__ void splitf(float x, unsigned short& hi, unsigned short& lo) {
    __nv_bfloat16 h = __float2bfloat16(x);
    __nv_bfloat16 l = __float2bfloat16(x - __bfloat162float(h));
    hi = __bfloat16_as_ushort(h);
    lo = __bfloat16_as_ushort(l);
}
__device__ __forceinline__ void split2(float p0, float p1, uint32_t& hp, uint32_t& lp) {
    unsigned short h0, l0, h1, l1;
    splitf(p0, h0, l0);
    splitf(p1, h1, l1);
    hp = ((uint32_t)h1 << 16) | h0;
    lp = ((uint32_t)l1 << 16) | l0;
}

// preload a warp's stage-1 A-operand fragments (16m x 64k) from smem
__device__ __forceinline__ void load_afrags(uint32_t f[4][4], uint32_t abase, int m0, int lane) {
    const uint32_t aaddr = abase + (uint32_t)(m0 + (lane & 15)) * ROWB
                         + (uint32_t)((lane >> 4) << 3) * 2;
#pragma unroll
    for (int kk = 0; kk < 4; kk++)
        ldsm4(f[kk][0], f[kk][1], f[kk][2], f[kk][3], aaddr + kk * 32);
}

// K=64 GEMM, TWO register A-fragment sets sharing each B fragment load.
__device__ __forceinline__ void gemm64_2a(float acc[8][4], const uint32_t a1[4][4],
                                          const uint32_t a2[4][4], uint32_t bbase, int lane) {
    const uint32_t baddr = bbase + (uint32_t)(((lane >> 4) << 3) + (lane & 7)) * ROWB
                         + (uint32_t)(((lane >> 3) & 1) << 3) * 2;
#pragma unroll
    for (int kk = 0; kk < 4; kk++) {
#pragma unroll
        for (int nt = 0; nt < 4; nt++) {
            uint32_t b0, b1, b2, b3;
            ldsm4(b0, b1, b2, b3, baddr + nt * 16 * ROWB + kk * 32);
            mma_bf16(acc[2 * nt],     a1[kk][0], a1[kk][1], a1[kk][2], a1[kk][3], b0, b1);
            mma_bf16(acc[2 * nt + 1], a1[kk][0], a1[kk][1], a1[kk][2], a1[kk][3], b2, b3);
            mma_bf16(acc[2 * nt],     a2[kk][0], a2[kk][1], a2[kk][2], a2[kk][3], b0, b1);
            mma_bf16(acc[2 * nt + 1], a2[kk][0], a2[kk][1], a2[kk][2], a2[kk][3], b2, b3);
        }
    }
}

// K=64 GEMM, ONE register A-fragment set.
__device__ __forceinline__ void gemm64_ra(float acc[8][4], const uint32_t af[4][4],
                                          uint32_t bbase, int lane) {
    const uint32_t baddr = bbase + (uint32_t)(((lane >> 4) << 3) + (lane & 7)) * ROWB
                         + (uint32_t)(((lane >> 3) & 1) << 3) * 2;
#pragma unroll
    for (int kk = 0; kk < 4; kk++) {
#pragma unroll
        for (int nt = 0; nt < 4; nt++) {
            uint32_t b0, b1, b2, b3;
            ldsm4(b0, b1, b2, b3, baddr + nt * 16 * ROWB + kk * 32);
            mma_bf16(acc[2 * nt],     af[kk][0], af[kk][1], af[kk][2], af[kk][3], b0, b1);
            mma_bf16(acc[2 * nt + 1], af[kk][0], af[kk][1], af[kk][2], af[kk][3], b2, b3);
        }
    }
}

// ---------------------------------------------------------------------------
// kernPre: merged r-transpose / V-split / w2-split (independent, run concurrently)
// grid 1088 x 256 thr: [0,512) kernR, [512,1024) kernVs, [1024,1088) kernWs
// ---------------------------------------------------------------------------
__global__ __launch_bounds__(256) void kernPre(const float* __restrict__ r,
                                               const float* __restrict__ v,
                                               const float* __restrict__ w2) {
    const int b = blockIdx.x;
    if (b < 512) {
        const int n = b >> 6, rr = b & 63;
        for (int t = threadIdx.x; t < IJ; t += 256)
            g_rT[(n * RD + rr) * IJ + t] = r[(n * IJ + t) * RD + rr];
    } else if (b < 1024) {
        for (int i = (b - 512) * 256 + threadIdx.x; i < NB * IJ * VD; i += 512 * 256) {
            unsigned short hi, lo;
            splitf(v[i], hi, lo);
            g_vhi[i] = hi;
            g_vlo[i] = lo;
        }
    } else {
        const int rr = b - 1024;
        const int h = threadIdx.x & 127;
        for (int x = threadIdx.x >> 7; x < XD; x += 2) {
            unsigned short hi, lo;
            splitf(w2[(x * RD + rr) * HD + h], hi, lo);
            g_w2hi[(rr * XD + x) * HD + h] = hi;
            g_w2lo[(rr * XD + x) * HD + h] = lo;
        }
    }
}

// ---------------------------------------------------------------------------
// kernA: A[n,rr,v,h] = sum_u w1*u (fp32, g_A); also zeroes the output.
// ---------------------------------------------------------------------------
__global__ __launch_bounds__(128) void kernA(const float* __restrict__ u,
                                             const float* __restrict__ w1,
                                             float* __restrict__ out) {
    const int rr = blockIdx.x, vv = blockIdx.y, h = threadIdx.x;
    out[(blockIdx.y * RD + blockIdx.x) * 128 + threadIdx.x] = 0.f;

    __shared__ float us[NB][UD];
    for (int idx = threadIdx.x; idx < NB * UD; idx += 128) {
        int n = idx >> 6, uu = idx & 63;
        us[n][uu] = u[((n * RD + rr) * UD + uu) * VD + vv];
    }
    __syncthreads();

    float acc[NB];
#pragma unroll
    for (int n = 0; n < NB; n++) acc[n] = 0.f;
    const float* w1p = w1 + (rr * UD * VD + vv) * HD + h;
#pragma unroll 4
    for (int uu = 0; uu < UD; uu++) {
        float w = w1p[uu * (VD * HD)];
#pragma unroll
        for (int n = 0; n < NB; n++) acc[n] = fmaf(w, us[n][uu], acc[n]);
    }
#pragma unroll
    for (int n = 0; n < NB; n++)
        g_A[((n * RD + rr) * VD + vv) * HD + h] = acc[n];
}

// ---------------------------------------------------------------------------
// kernT: transpose + split g_A[n][rr][v][h] -> g_ahi/lo[n][rr][h][v]
// ---------------------------------------------------------------------------
__global__ __launch_bounds__(256) void kernT() {
    const int n = blockIdx.x, rr = blockIdx.y;
    __shared__ float tile[VD][HD + 1];
    const float* src = g_A + (size_t)(n * RD + rr) * VD * HD;
    for (int idx = threadIdx.x; idx < VD * HD; idx += 256) {
        int v = idx >> 7, h = idx & 127;
        tile[v][h] = src[idx];
    }
    __syncthreads();
    const size_t obase = (size_t)(n * RD + rr) * HD * VD;
    for (int idx = threadIdx.x; idx < HD * VD; idx += 256) {
        int h = idx >> 6, v = idx & 63;
        unsigned short hi, lo;
        splitf(tile[v][h], hi, lo);
        g_ahi[obase + idx] = hi;
        g_alo[obase + idx] = lo;
    }
}

// ---------------------------------------------------------------------------
// kernB: 256 thr, tile 128m x 64c, cp.async double-buffered A/W tiles,
// V fragments register-hoisted, B fragments shared across split terms.
// ---------------------------------------------------------------------------
extern __shared__ unsigned char smemB[];

__device__ __forceinline__ void issue_fills(uint32_t sbuf, int n, int rr, int h0g, int tid) {
    const unsigned short* a1 = g_ahi + ((size_t)(n * RD + rr) * HD + h0g) * VD;
    const unsigned short* a2 = g_alo + ((size_t)(n * RD + rr) * HD + h0g) * VD;
#pragma unroll
    for (int j = 0; j < 2; j++) {
        int i = tid + j * 256;               // 0..511
        int row = i >> 3, c = i & 7;
        uint32_t dst = sbuf + row * ROWB + c * 16;
        cp16(dst,             a1 + i * 8);
        cp16(dst + TILEB,     a2 + i * 8);
        const unsigned short* w1p = g_w2hi + (size_t)(rr * XD + row) * HD + h0g + c * 8;
        const unsigned short* w2p = g_w2lo + (size_t)(rr * XD + row) * HD + h0g + c * 8;
        cp16(dst + 2 * TILEB, w1p);
        cp16(dst + 3 * TILEB, w2p);
    }
}

__global__ __launch_bounds__(256, 2) void kernB(float* __restrict__ out) {
    const uint32_t sb = smem_u32(smemB);
    const int tid = threadIdx.x, lane = tid & 31, w = tid >> 5;
    const int tile = blockIdx.x, n = blockIdx.y, z = blockIdx.z;
    const int token0 = tile * TM;
    const int h0g = (z & 1) * HC;
    const int rr0 = (z >> 1) * RRG;
    const int m0 = w * 16;
    const int mrow = lane >> 2;              // 0..7

    // prefetch rr0 into buffer 0 (start L2 loads early)
    issue_fills(sb + SOFF_BUF, n, rr0, h0g, tid);
    CP_COMMIT();

    // V tile fill (once): 128 rows x 128B, 144B stride
    {
        const uint4* s1 = (const uint4*)(g_vhi + (size_t)(n * IJ + token0) * VD);
        const uint4* s2 = (const uint4*)(g_vlo + (size_t)(n * IJ + token0) * VD);
#pragma unroll
        for (int j = 0; j < 4; j++) {
            int i = tid + j * 256;           // 0..1023
            int row = i >> 3, c = i & 7;
            *(uint4*)(smemB + SOFF_VHI + row * ROWB + c * 16) = s1[i];
            *(uint4*)(smemB + SOFF_VLO + row * ROWB + c * 16) = s2[i];
        }
    }
    __syncthreads();

    // hoist V fragments into registers (invariant across all rr)
    uint32_t vhi[4][4], vlo[4][4];
    load_afrags(vhi, sb + SOFF_VHI, m0, lane);
    load_afrags(vlo, sb + SOFF_VLO, m0, lane);

    float oc[8][4];
#pragma unroll
    for (int t = 0; t < 8; t++)
#pragma unroll
        for (int j = 0; j < 4; j++) oc[t][j] = 0.f;

    for (int rl = 0; rl < RRG; rl++) {
        const int rr = rr0 + rl;
        const uint32_t sbuf = sb + SOFF_BUF + (rl & 1) * BUFB;
        const uint32_t snxt = sb + SOFF_BUF + ((rl & 1) ^ 1) * BUFB;

        __syncthreads();   // prev iter compute done (next buffer free for overwrite)
        if (rl + 1 < RRG) {
            issue_fills(snxt, n, rr + 1, h0g, tid);
            CP_COMMIT();
            CP_WAIT1();    // current buffer's group complete
        } else {
            CP_WAIT0();
        }
        const float rsc0 = g_rT[(n * RD + rr) * IJ + token0 + m0 + mrow];
        const float rsc8 = g_rT[(n * RD + rr) * IJ + token0 + m0 + mrow + 8];
        __syncthreads();   // current buffer visible to all warps

        // ---- stage 1: P[16m x 64h], 3-term split, shared B frags ----
        float pc[8][4];
#pragma unroll
        for (int t = 0; t < 8; t++)
#pragma unroll
            for (int j = 0; j < 4; j++) pc[t][j] = 0.f;

        gemm64_2a(pc, vhi, vlo, sbuf,         lane);   // (Vhi+Vlo) * Ahi
        gemm64_ra(pc, vhi,      sbuf + TILEB, lane);   // Vhi * Alo

        // ---- epilogue in registers: relu * r, split -> stage-2 A fragments ----
        uint32_t phi[4][4], plo[4][4];
#pragma unroll
        for (int kk = 0; kk < 4; kk++) {
            split2(fmaxf(pc[2 * kk][0], 0.f) * rsc0, fmaxf(pc[2 * kk][1], 0.f) * rsc0,
                   phi[kk][0], plo[kk][0]);
            split2(fmaxf(pc[2 * kk][2], 0.f) * rsc8, fmaxf(pc[2 * kk][3], 0.f) * rsc8,
                   phi[kk][1], plo[kk][1]);
            split2(fmaxf(pc[2 * kk + 1][0], 0.f) * rsc0, fmaxf(pc[2 * kk + 1][1], 0.f) * rsc0,
                   phi[kk][2], plo[kk][2]);
            split2(fmaxf(pc[2 * kk + 1][2], 0.f) * rsc8, fmaxf(pc[2 * kk + 1][3], 0.f) * rsc8,
                   phi[kk][3], plo[kk][3]);
        }

        // ---- stage 2: OUT[16m x 64x] += P * W2^T, shared B frags ----
        gemm64_2a(oc, phi, plo, sbuf + 2 * TILEB, lane);   // (Phi+Plo) * Whi
        gemm64_ra(oc, phi,      sbuf + 3 * TILEB, lane);   // Phi * Wlo
    }

    // final epilogue: 4 partial CTAs per out element (2 hblk x 2 rr-halves)
    {
        float* op = out + (size_t)(n * IJ + token0 + m0 + mrow) * XD;
#pragma unroll
        for (int nt = 0; nt < 8; nt++) {
            const int x = nt * 8 + 2 * (lane & 3);
            atomicAdd(op + x,     oc[nt][0]);
            atomicAdd(op + x + 1, oc[nt][1]);
            atomicAdd(op + 8 * XD + x,     oc[nt][2]);
            atomicAdd(op + 8 * XD + x + 1, oc[nt][3]);
        }
    }
}

// ---------------------------------------------------------------------------
extern "C" void kernel_launch(void* const* d_in, const int* in_sizes, int n_in,
                              void* d_out, int out_size) {
    const float* r  = (const float*)d_in[0];
    const float* u  = (const float*)d_in[1];
    const float* v  = (const float*)d_in[2];
    const float* w1 = (const float*)d_in[3];
    const float* w2 = (const float*)d_in[4];
    float* out = (float*)d_out;
    (void)in_sizes; (void)n_in; (void)out_size;

    static int attr_done = 0;
    if (!attr_done) {
        cudaFuncSetAttribute(kernB, cudaFuncAttributeMaxDynamicSharedMemorySize, SMEM_TOTAL);
        attr_done = 1;
    }

    kernPre<<<1088, 256>>>(r, v, w2);
    kernA<<<dim3(RD, VD), 128>>>(u, w1, out);
    kernT<<<dim3(NB, RD), 256>>>();
    kernB<<<dim3(IJ / TM, NB, 4), 256, SMEM_TOTAL>>>(out);
}

// round 11
// speedup vs baseline: 2.9132x; 1.0191x over previous
#include <cuda_runtime.h>
#include <cuda_bf16.h>
#include <cstdint>

#define RD 64
#define UD 64
#define VD 64
#define HD 128
#define XD 64
#define NB 8
#define IJ 1024
#define TM 128           // token tile
#define HC 64            // h per CTA (hblk)
#define RRG 32           // rr per CTA

// smem: V tiles (128 rows) + double-buffered A/W tiles (64 rows), 144B row stride
#define ROWB 144
#define VTILEB (128 * ROWB)        // 18432
#define TILEB  (64 * ROWB)         // 9216
#define SOFF_VHI 0
#define SOFF_VLO VTILEB
#define SOFF_BUF (2 * VTILEB)      // two buffers of 4 tiles each
#define BUFB (4 * TILEB)           // 36864: [AHI][ALO][WHI][WLO]
#define SMEM_TOTAL (2 * VTILEB + 2 * BUFB)   // 110592 -> 2 CTAs/SM

// ---------------- gmem scratch ----------------
__device__ float g_A[NB * RD * VD * HD];                       // fp32 A, 16.8MB
__device__ float g_rT[NB * RD * IJ];                           // r^T, 2MB
__device__ __align__(16) unsigned short g_ahi[NB * RD * HD * VD];  // A split [n][rr][h][v]
__device__ __align__(16) unsigned short g_alo[NB * RD * HD * VD];
__device__ __align__(16) unsigned short g_vhi[NB * IJ * VD];       // V split [n][m][v]
__device__ __align__(16) unsigned short g_vlo[NB * IJ * VD];
__device__ __align__(16) unsigned short g_w2hi[RD * XD * HD];      // w2 split [rr][x][h]
__device__ __align__(16) unsigned short g_w2lo[RD * XD * HD];

// ---------------- helpers ----------------
__device__ __forceinline__ uint32_t smem_u32(const void* p) {
    uint32_t a;
    asm("{ .reg .u64 t; cvta.to.shared.u64 t, %1; cvt.u32.u64 %0, t; }" : "=r"(a) : "l"(p));
    return a;
}
__device__ __forceinline__ void cp16(uint32_t dst, const void* src) {
    asm volatile("cp.async.cg.shared.global [%0], [%1], 16;" :: "r"(dst), "l"(src));
}
#define CP_COMMIT() asm volatile("cp.async.commit_group;" ::: "memory")
#define CP_WAIT1()  asm volatile("cp.async.wait_group 1;" ::: "memory")
#define CP_WAIT0()  asm volatile("cp.async.wait_group 0;" ::: "memory")

__device__ __forceinline__ void ldsm4(uint32_t& r0, uint32_t& r1, uint32_t& r2, uint32_t& r3,
                                      uint32_t addr) {
    asm volatile("ldmatrix.sync.aligned.m8n8.x4.shared.b16 {%0,%1,%2,%3}, [%4];"
                 : "=r"(r0), "=r"(r1), "=r"(r2), "=r"(r3) : "r"(addr));
}
__device__ __forceinline__ void mma_bf16(float* d, uint32_t a0, uint32_t a1, uint32_t a2,
                                         uint32_t a3, uint32_t b0, uint32_t b1) {
    asm volatile(
        "mma.sync.aligned.m16n8k16.row.col.f32.bf16.bf16.f32 "
        "{%0,%1,%2,%3}, {%4,%5,%6,%7}, {%8,%9}, {%0,%1,%2,%3};"
        : "+f"(d[0]), "+f"(d[1]), "+f"(d[2]), "+f"(d[3])
        : "r"(a0), "r"(a1), "r"(a2), "r"(a3), "r"(b0), "r"(b1));
}
__device__ __forceinline__ void splitf(float x, unsigned short& hi, unsigned short& lo) {
    __nv_bfloat16 h = __float2bfloat16(x);
    __nv_bfloat16 l = __float2bfloat16(x - __bfloat162float(h));
    hi = __bfloat16_as_ushort(h);
    lo = __bfloat16_as_ushort(l);
}
// packed split: hp = {bf16(p1), bf16(p0)}, lp = residuals, via cvt.rn.bf16x2
__device__ __forceinline__ void split2(float p0, float p1, uint32_t& hp, uint32_t& lp) {
    asm("cvt.rn.bf16x2.f32 %0, %1, %2;" : "=r"(hp) : "f"(p1), "f"(p0));
    float h0 = __uint_as_float(hp << 16);
    float h1 = __uint_as_float(hp & 0xffff0000u);
    float l0 = p0 - h0, l1 = p1 - h1;
    asm("cvt.rn.bf16x2.f32 %0, %1, %2;" : "=r"(lp) : "f"(l1), "f"(l0));
}

// preload a warp's stage-1 A-operand fragments (16m x 64k) from smem
__device__ __forceinline__ void load_afrags(uint32_t f[4][4], uint32_t abase, int m0, int lane) {
    const uint32_t aaddr = abase + (uint32_t)(m0 + (lane & 15)) * ROWB
                         + (uint32_t)((lane >> 4) << 3) * 2;
#pragma unroll
    for (int kk = 0; kk < 4; kk++)
        ldsm4(f[kk][0], f[kk][1], f[kk][2], f[kk][3], aaddr + kk * 32);
}

// K=64 GEMM, TWO register A-fragment sets sharing each B fragment load.
__device__ __forceinline__ void gemm64_2a(float acc[8][4], const uint32_t a1[4][4],
                                          const uint32_t a2[4][4], uint32_t bbase, int lane) {
    const uint32_t baddr = bbase + (uint32_t)(((lane >> 4) << 3) + (lane & 7)) * ROWB
                         + (uint32_t)(((lane >> 3) & 1) << 3) * 2;
#pragma unroll
    for (int kk = 0; kk < 4; kk++) {
#pragma unroll
        for (int nt = 0; nt < 4; nt++) {
            uint32_t b0, b1, b2, b3;
            ldsm4(b0, b1, b2, b3, baddr + nt * 16 * ROWB + kk * 32);
            mma_bf16(acc[2 * nt],     a1[kk][0], a1[kk][1], a1[kk][2], a1[kk][3], b0, b1);
            mma_bf16(acc[2 * nt + 1], a1[kk][0], a1[kk][1], a1[kk][2], a1[kk][3], b2, b3);
            mma_bf16(acc[2 * nt],     a2[kk][0], a2[kk][1], a2[kk][2], a2[kk][3], b0, b1);
            mma_bf16(acc[2 * nt + 1], a2[kk][0], a2[kk][1], a2[kk][2], a2[kk][3], b2, b3);
        }
    }
}

// K=64 GEMM, ONE register A-fragment set.
__device__ __forceinline__ void gemm64_ra(float acc[8][4], const uint32_t af[4][4],
                                          uint32_t bbase, int lane) {
    const uint32_t baddr = bbase + (uint32_t)(((lane >> 4) << 3) + (lane & 7)) * ROWB
                         + (uint32_t)(((lane >> 3) & 1) << 3) * 2;
#pragma unroll
    for (int kk = 0; kk < 4; kk++) {
#pragma unroll
        for (int nt = 0; nt < 4; nt++) {
            uint32_t b0, b1, b2, b3;
            ldsm4(b0, b1, b2, b3, baddr + nt * 16 * ROWB + kk * 32);
            mma_bf16(acc[2 * nt],     af[kk][0], af[kk][1], af[kk][2], af[kk][3], b0, b1);
            mma_bf16(acc[2 * nt + 1], af[kk][0], af[kk][1], af[kk][2], af[kk][3], b2, b3);
        }
    }
}

// ---------------------------------------------------------------------------
// kernPre: merged r-transpose / V-split / w2-split (independent, run concurrently)
// ---------------------------------------------------------------------------
__global__ __launch_bounds__(256) void kernPre(const float* __restrict__ r,
                                               const float* __restrict__ v,
                                               const float* __restrict__ w2) {
    const int b = blockIdx.x;
    if (b < 512) {
        const int n = b >> 6, rr = b & 63;
        for (int t = threadIdx.x; t < IJ; t += 256)
            g_rT[(n * RD + rr) * IJ + t] = r[(n * IJ + t) * RD + rr];
    } else if (b < 1024) {
        for (int i = (b - 512) * 256 + threadIdx.x; i < NB * IJ * VD; i += 512 * 256) {
            unsigned short hi, lo;
            splitf(v[i], hi, lo);
            g_vhi[i] = hi;
            g_vlo[i] = lo;
        }
    } else {
        const int rr = b - 1024;
        const int h = threadIdx.x & 127;
        for (int x = threadIdx.x >> 7; x < XD; x += 2) {
            unsigned short hi, lo;
            splitf(w2[(x * RD + rr) * HD + h], hi, lo);
            g_w2hi[(rr * XD + x) * HD + h] = hi;
            g_w2lo[(rr * XD + x) * HD + h] = lo;
        }
    }
}

// ---------------------------------------------------------------------------
// kernA: A[n,rr,v,h] = sum_u w1*u (fp32, g_A); also zeroes the output.
// ---------------------------------------------------------------------------
__global__ __launch_bounds__(128) void kernA(const float* __restrict__ u,
                                             const float* __restrict__ w1,
                                             float* __restrict__ out) {
    const int rr = blockIdx.x, vv = blockIdx.y, h = threadIdx.x;
    out[(blockIdx.y * RD + blockIdx.x) * 128 + threadIdx.x] = 0.f;

    __shared__ float us[NB][UD];
    for (int idx = threadIdx.x; idx < NB * UD; idx += 128) {
        int n = idx >> 6, uu = idx & 63;
        us[n][uu] = u[((n * RD + rr) * UD + uu) * VD + vv];
    }
    __syncthreads();

    float acc[NB];
#pragma unroll
    for (int n = 0; n < NB; n++) acc[n] = 0.f;
    const float* w1p = w1 + (rr * UD * VD + vv) * HD + h;
#pragma unroll 8
    for (int uu = 0; uu < UD; uu++) {
        float w = w1p[uu * (VD * HD)];
#pragma unroll
        for (int n = 0; n < NB; n++) acc[n] = fmaf(w, us[n][uu], acc[n]);
    }
#pragma unroll
    for (int n = 0; n < NB; n++)
        g_A[((n * RD + rr) * VD + vv) * HD + h] = acc[n];
}

// ---------------------------------------------------------------------------
// kernT: transpose + split g_A[n][rr][v][h] -> g_ahi/lo[n][rr][h][v]
// ---------------------------------------------------------------------------
__global__ __launch_bounds__(256) void kernT() {
    const int n = blockIdx.x, rr = blockIdx.y;
    __shared__ float tile[VD][HD + 1];
    const float* src = g_A + (size_t)(n * RD + rr) * VD * HD;
    for (int idx = threadIdx.x; idx < VD * HD; idx += 256) {
        int v = idx >> 7, h = idx & 127;
        tile[v][h] = src[idx];
    }
    __syncthreads();
    const size_t obase = (size_t)(n * RD + rr) * HD * VD;
    for (int idx = threadIdx.x; idx < HD * VD; idx += 256) {
        int h = idx >> 6, v = idx & 63;
        unsigned short hi, lo;
        splitf(tile[v][h], hi, lo);
        g_ahi[obase + idx] = hi;
        g_alo[obase + idx] = lo;
    }
}

// ---------------------------------------------------------------------------
// kernB: 256 thr, tile 128m x 64c, cp.async double-buffered A/W tiles,
// V fragments register-hoisted, B fragments shared, phase-staggered rr ring.
// ---------------------------------------------------------------------------
extern __shared__ unsigned char smemB[];

__device__ __forceinline__ void issue_fills(uint32_t sbuf, int n, int rr, int h0g, int tid) {
    const unsigned short* a1 = g_ahi + ((size_t)(n * RD + rr) * HD + h0g) * VD;
    const unsigned short* a2 = g_alo + ((size_t)(n * RD + rr) * HD + h0g) * VD;
#pragma unroll
    for (int j = 0; j < 2; j++) {
        int i = tid + j * 256;               // 0..511
        int row = i >> 3, c = i & 7;
        uint32_t dst = sbuf + row * ROWB + c * 16;
        cp16(dst,             a1 + i * 8);
        cp16(dst + TILEB,     a2 + i * 8);
        const unsigned short* w1p = g_w2hi + (size_t)(rr * XD + row) * HD + h0g + c * 8;
        const unsigned short* w2p = g_w2lo + (size_t)(rr * XD + row) * HD + h0g + c * 8;
        cp16(dst + 2 * TILEB, w1p);
        cp16(dst + 3 * TILEB, w2p);
    }
}

__global__ __launch_bounds__(256, 2) void kernB(float* __restrict__ out) {
    const uint32_t sb = smem_u32(smemB);
    const int tid = threadIdx.x, lane = tid & 31, w = tid >> 5;
    const int tile = blockIdx.x, n = blockIdx.y, z = blockIdx.z;
    const int token0 = tile * TM;
    const int h0g = (z & 1) * HC;
    const int rr0 = (z >> 1) * RRG;
    const int m0 = w * 16;
    const int mrow = lane >> 2;              // 0..7
    // stagger co-resident CTAs' phase through the rr ring (sum order only)
    const int stag = (blockIdx.x & 1) * (RRG / 2);

    // prefetch first rr into buffer 0 (start L2 loads early)
    issue_fills(sb + SOFF_BUF, n, rr0 + stag, h0g, tid);
    CP_COMMIT();

    // V tile fill (once): 128 rows x 128B, 144B stride
    {
        const uint4* s1 = (const uint4*)(g_vhi + (size_t)(n * IJ + token0) * VD);
        const uint4* s2 = (const uint4*)(g_vlo + (size_t)(n * IJ + token0) * VD);
#pragma unroll
        for (int j = 0; j < 4; j++) {
            int i = tid + j * 256;           // 0..1023
            int row = i >> 3, c = i & 7;
            *(uint4*)(smemB + SOFF_VHI + row * ROWB + c * 16) = s1[i];
            *(uint4*)(smemB + SOFF_VLO + row * ROWB + c * 16) = s2[i];
        }
    }
    __syncthreads();

    // hoist V fragments into registers (invariant across all rr)
    uint32_t vhi[4][4], vlo[4][4];
    load_afrags(vhi, sb + SOFF_VHI, m0, lane);
    load_afrags(vlo, sb + SOFF_VLO, m0, lane);

    float oc[8][4];
#pragma unroll
    for (int t = 0; t < 8; t++)
#pragma unroll
        for (int j = 0; j < 4; j++) oc[t][j] = 0.f;

    for (int rl = 0; rl < RRG; rl++) {
        const int rr = rr0 + ((rl + stag) & (RRG - 1));
        const uint32_t sbuf = sb + SOFF_BUF + (rl & 1) * BUFB;
        const uint32_t snxt = sb + SOFF_BUF + ((rl & 1) ^ 1) * BUFB;

        // r scales for this rr (early: hide L2 latency under fills + waits)
        const float rsc0 = g_rT[(n * RD + rr) * IJ + token0 + m0 + mrow];
        const float rsc8 = g_rT[(n * RD + rr) * IJ + token0 + m0 + mrow + 8];

        __syncthreads();   // prev iter compute done (next buffer free for overwrite)
        if (rl + 1 < RRG) {
            issue_fills(snxt, n, rr0 + ((rl + 1 + stag) & (RRG - 1)), h0g, tid);
            CP_COMMIT();
            CP_WAIT1();    // current buffer's group complete
        } else {
            CP_WAIT0();
        }
        __syncthreads();   // current buffer visible to all warps

        // ---- stage 1: P[16m x 64h], 3-term split, shared B frags ----
        float pc[8][4];
#pragma unroll
        for (int t = 0; t < 8; t++)
#pragma unroll
            for (int j = 0; j < 4; j++) pc[t][j] = 0.f;

        gemm64_2a(pc, vhi, vlo, sbuf,         lane);   // (Vhi+Vlo) * Ahi
        gemm64_ra(pc, vhi,      sbuf + TILEB, lane);   // Vhi * Alo

        // ---- epilogue in registers: relu * r, split -> stage-2 A fragments ----
        uint32_t phi[4][4], plo[4][4];
#pragma unroll
        for (int kk = 0; kk < 4; kk++) {
            split2(fmaxf(pc[2 * kk][0], 0.f) * rsc0, fmaxf(pc[2 * kk][1], 0.f) * rsc0,
                   phi[kk][0], plo[kk][0]);
            split2(fmaxf(pc[2 * kk][2], 0.f) * rsc8, fmaxf(pc[2 * kk][3], 0.f) * rsc8,
                   phi[kk][1], plo[kk][1]);
            split2(fmaxf(pc[2 * kk + 1][0], 0.f) * rsc0, fmaxf(pc[2 * kk + 1][1], 0.f) * rsc0,
                   phi[kk][2], plo[kk][2]);
            split2(fmaxf(pc[2 * kk + 1][2], 0.f) * rsc8, fmaxf(pc[2 * kk + 1][3], 0.f) * rsc8,
                   phi[kk][3], plo[kk][3]);
        }

        // ---- stage 2: OUT[16m x 64x] += P * W2^T, shared B frags ----
        gemm64_2a(oc, phi, plo, sbuf + 2 * TILEB, lane);   // (Phi+Plo) * Whi
        gemm64_ra(oc, phi,      sbuf + 3 * TILEB, lane);   // Phi * Wlo
    }

    // final epilogue: 4 partial CTAs per out element (2 hblk x 2 rr-halves)
    {
        float* op = out + (size_t)(n * IJ + token0 + m0 + mrow) * XD;
#pragma unroll
        for (int nt = 0; nt < 8; nt++) {
            const int x = nt * 8 + 2 * (lane & 3);
            atomicAdd(op + x,     oc[nt][0]);
            atomicAdd(op + x + 1, oc[nt][1]);
            atomicAdd(op + 8 * XD + x,     oc[nt][2]);
            atomicAdd(op + 8 * XD + x + 1, oc[nt][3]);
        }
    }
}

// ---------------------------------------------------------------------------
extern "C" void kernel_launch(void* const* d_in, const int* in_sizes, int n_in,
                              void* d_out, int out_size) {
    const float* r  = (const float*)d_in[0];
    const float* u  = (const float*)d_in[1];
    const float* v  = (const float*)d_in[2];
    const float* w1 = (const float*)d_in[3];
    const float* w2 = (const float*)d_in[4];
    float* out = (float*)d_out;
    (void)in_sizes; (void)n_in; (void)out_size;

    static int attr_done = 0;
    if (!attr_done) {
        cudaFuncSetAttribute(kernB, cudaFuncAttributeMaxDynamicSharedMemorySize, SMEM_TOTAL);
        attr_done = 1;
    }

    kernPre<<<1088, 256>>>(r, v, w2);
    kernA<<<dim3(RD, VD), 128>>>(u, w1, out);
    kernT<<<dim3(NB, RD), 256>>>();
    kernB<<<dim3(IJ / TM, NB, 4), 256, SMEM_TOTAL>>>(out);
}

// round 12
// speedup vs baseline: 3.1119x; 1.0682x over previous
#include <cuda_runtime.h>
#include <cuda_bf16.h>
#include <cstdint>

#define RD 64
#define UD 64
#define VD 64
#define HD 128
#define XD 64
#define NB 8
#define IJ 1024
#define TM 128           // token tile
#define HC 64            // h per CTA (hblk)
#define RRG 32           // rr per CTA

// smem: V tiles (128 rows) + double-buffered A/W tiles (64 rows), 144B row stride
#define ROWB 144
#define VTILEB (128 * ROWB)        // 18432
#define TILEB  (64 * ROWB)         // 9216
#define SOFF_VHI 0
#define SOFF_VLO VTILEB
#define SOFF_BUF (2 * VTILEB)      // two buffers of 4 tiles each
#define BUFB (4 * TILEB)           // 36864: [AHI][ALO][WHI][WLO]
#define SMEM_TOTAL (2 * VTILEB + 2 * BUFB)   // 110592 -> 2 CTAs/SM

// ---------------- gmem scratch ----------------
__device__ float g_rT[NB * RD * IJ];                               // r^T, 2MB
__device__ __align__(16) unsigned short g_ahi[NB * RD * VD * HD];  // A split [n][rr][v][h]
__device__ __align__(16) unsigned short g_alo[NB * RD * VD * HD];
__device__ __align__(16) unsigned short g_vhi[NB * IJ * VD];       // V split [n][m][v]
__device__ __align__(16) unsigned short g_vlo[NB * IJ * VD];
__device__ __align__(16) unsigned short g_w2hi[RD * XD * HD];      // w2 split [rr][x][h]
__device__ __align__(16) unsigned short g_w2lo[RD * XD * HD];

// ---------------- helpers ----------------
__device__ __forceinline__ uint32_t smem_u32(const void* p) {
    uint32_t a;
    asm("{ .reg .u64 t; cvta.to.shared.u64 t, %1; cvt.u32.u64 %0, t; }" : "=r"(a) : "l"(p));
    return a;
}
__device__ __forceinline__ void cp16(uint32_t dst, const void* src) {
    asm volatile("cp.async.cg.shared.global [%0], [%1], 16;" :: "r"(dst), "l"(src));
}
#define CP_COMMIT() asm volatile("cp.async.commit_group;" ::: "memory")
#define CP_WAIT1()  asm volatile("cp.async.wait_group 1;" ::: "memory")
#define CP_WAIT0()  asm volatile("cp.async.wait_group 0;" ::: "memory")

__device__ __forceinline__ void ldsm4(uint32_t& r0, uint32_t& r1, uint32_t& r2, uint32_t& r3,
                                      uint32_t addr) {
    asm volatile("ldmatrix.sync.aligned.m8n8.x4.shared.b16 {%0,%1,%2,%3}, [%4];"
                 : "=r"(r0), "=r"(r1), "=r"(r2), "=r"(r3) : "r"(addr));
}
__device__ __forceinline__ void ldsm4t(uint32_t& r0, uint32_t& r1, uint32_t& r2, uint32_t& r3,
                                       uint32_t addr) {
    asm volatile("ldmatrix.sync.aligned.m8n8.x4.trans.shared.b16 {%0,%1,%2,%3}, [%4];"
                 : "=r"(r0), "=r"(r1), "=r"(r2), "=r"(r3) : "r"(addr));
}
__device__ __forceinline__ void mma_bf16(float* d, const uint32_t a[4],
                                         uint32_t b0, uint32_t b1) {
    asm volatile(
        "mma.sync.aligned.m16n8k16.row.col.f32.bf16.bf16.f32 "
        "{%0,%1,%2,%3}, {%4,%5,%6,%7}, {%8,%9}, {%0,%1,%2,%3};"
        : "+f"(d[0]), "+f"(d[1]), "+f"(d[2]), "+f"(d[3])
        : "r"(a[0]), "r"(a[1]), "r"(a[2]), "r"(a[3]), "r"(b0), "r"(b1));
}
__device__ __forceinline__ void splitf(float x, unsigned short& hi, unsigned short& lo) {
    __nv_bfloat16 h = __float2bfloat16(x);
    __nv_bfloat16 l = __float2bfloat16(x - __bfloat162float(h));
    hi = __bfloat16_as_ushort(h);
    lo = __bfloat16_as_ushort(l);
}
// packed split: hp = {bf16(p1), bf16(p0)}, lp = residuals
__device__ __forceinline__ void split2(float p0, float p1, uint32_t& hp, uint32_t& lp) {
    asm("cvt.rn.bf16x2.f32 %0, %1, %2;" : "=r"(hp) : "f"(p1), "f"(p0));
    float h0 = __uint_as_float(hp << 16);
    float h1 = __uint_as_float(hp & 0xffff0000u);
    float l0 = p0 - h0, l1 = p1 - h1;
    asm("cvt.rn.bf16x2.f32 %0, %1, %2;" : "=r"(lp) : "f"(l1), "f"(l0));
}

// preload a warp's stage-1 A-operand fragments (16m x 64k) from smem (row-major tile)
__device__ __forceinline__ void load_afrags(uint32_t f[4][4], uint32_t abase, int m0, int lane) {
    const uint32_t aaddr = abase + (uint32_t)(m0 + (lane & 15)) * ROWB
                         + (uint32_t)((lane >> 4) << 3) * 2;
#pragma unroll
    for (int kk = 0; kk < 4; kk++)
        ldsm4(f[kk][0], f[kk][1], f[kk][2], f[kk][3], aaddr + kk * 32);
}

// ---------------------------------------------------------------------------
// kernPre: merged r-transpose / V-split / w2-split
// ---------------------------------------------------------------------------
__global__ __launch_bounds__(256) void kernPre(const float* __restrict__ r,
                                               const float* __restrict__ v,
                                               const float* __restrict__ w2) {
    const int b = blockIdx.x;
    if (b < 512) {
        const int n = b >> 6, rr = b & 63;
        for (int t = threadIdx.x; t < IJ; t += 256)
            g_rT[(n * RD + rr) * IJ + t] = r[(n * IJ + t) * RD + rr];
    } else if (b < 1024) {
        for (int i = (b - 512) * 256 + threadIdx.x; i < NB * IJ * VD; i += 512 * 256) {
            unsigned short hi, lo;
            splitf(v[i], hi, lo);
            g_vhi[i] = hi;
            g_vlo[i] = lo;
        }
    } else {
        const int rr = b - 1024;
        const int h = threadIdx.x & 127;
        for (int x = threadIdx.x >> 7; x < XD; x += 2) {
            unsigned short hi, lo;
            splitf(w2[(x * RD + rr) * HD + h], hi, lo);
            g_w2hi[(rr * XD + x) * HD + h] = hi;
            g_w2lo[(rr * XD + x) * HD + h] = lo;
        }
    }
}

// ---------------------------------------------------------------------------
// kernA: A[n,rr,v,h] = sum_u w1*u, split bf16 written DIRECTLY in [n][rr][v][h]
// (k-major for trans-ldsm consumption). Also zeroes the output.
// ---------------------------------------------------------------------------
__global__ __launch_bounds__(128) void kernA(const float* __restrict__ u,
                                             const float* __restrict__ w1,
                                             float* __restrict__ out) {
    const int rr = blockIdx.x, vv = blockIdx.y, h = threadIdx.x;
    out[(blockIdx.y * RD + blockIdx.x) * 128 + threadIdx.x] = 0.f;

    __shared__ float us[NB][UD];
    for (int idx = threadIdx.x; idx < NB * UD; idx += 128) {
        int n = idx >> 6, uu = idx & 63;
        us[n][uu] = u[((n * RD + rr) * UD + uu) * VD + vv];
    }
    __syncthreads();

    float acc[NB];
#pragma unroll
    for (int n = 0; n < NB; n++) acc[n] = 0.f;
    const float* w1p = w1 + (rr * UD * VD + vv) * HD + h;
#pragma unroll 8
    for (int uu = 0; uu < UD; uu++) {
        float w = w1p[uu * (VD * HD)];
#pragma unroll
        for (int n = 0; n < NB; n++) acc[n] = fmaf(w, us[n][uu], acc[n]);
    }
#pragma unroll
    for (int n = 0; n < NB; n++) {
        unsigned short hi, lo;
        splitf(acc[n], hi, lo);
        const size_t o = ((size_t)(n * RD + rr) * VD + vv) * HD + h;
        g_ahi[o] = hi;
        g_alo[o] = lo;
    }
}

// ---------------------------------------------------------------------------
// kernB: 256 thr, tile 128m x 64c, cp.async double-buffered A/W tiles,
// V fragments register-hoisted, per-h-chunk pipelined s1->epilogue->s2.
// ---------------------------------------------------------------------------
extern __shared__ unsigned char smemB[];

__device__ __forceinline__ void issue_fills(uint32_t sbuf, int n, int rr, int h0g, int tid) {
    const unsigned short* a1 = g_ahi + ((size_t)(n * RD + rr) * VD) * HD + h0g;
    const unsigned short* a2 = g_alo + ((size_t)(n * RD + rr) * VD) * HD + h0g;
#pragma unroll
    for (int j = 0; j < 2; j++) {
        int i = tid + j * 256;               // 0..511
        int row = i >> 3, c = i & 7;
        uint32_t dst = sbuf + row * ROWB + c * 16;
        cp16(dst,             a1 + (size_t)row * HD + c * 8);   // A tile [v][h-slice]
        cp16(dst + TILEB,     a2 + (size_t)row * HD + c * 8);
        const unsigned short* w1p = g_w2hi + (size_t)(rr * XD + row) * HD + h0g + c * 8;
        const unsigned short* w2p = g_w2lo + (size_t)(rr * XD + row) * HD + h0g + c * 8;
        cp16(dst + 2 * TILEB, w1p);
        cp16(dst + 3 * TILEB, w2p);
    }
}

__global__ __launch_bounds__(256, 2) void kernB(float* __restrict__ out) {
    const uint32_t sb = smem_u32(smemB);
    const int tid = threadIdx.x, lane = tid & 31, w = tid >> 5;
    const int tile = blockIdx.x, n = blockIdx.y, z = blockIdx.z;
    const int token0 = tile * TM;
    const int h0g = (z & 1) * HC;
    const int rr0 = (z >> 1) * RRG;
    const int m0 = w * 16;
    const int mrow = lane >> 2;              // 0..7
    const int stag = (blockIdx.x & 1) * (RRG / 2);

    // prefetch first rr into buffer 0
    issue_fills(sb + SOFF_BUF, n, rr0 + stag, h0g, tid);
    CP_COMMIT();

    // V tile fill (once): 128 rows x 128B, 144B stride
    {
        const uint4* s1 = (const uint4*)(g_vhi + (size_t)(n * IJ + token0) * VD);
        const uint4* s2 = (const uint4*)(g_vlo + (size_t)(n * IJ + token0) * VD);
#pragma unroll
        for (int j = 0; j < 4; j++) {
            int i = tid + j * 256;           // 0..1023
            int row = i >> 3, c = i & 7;
            *(uint4*)(smemB + SOFF_VHI + row * ROWB + c * 16) = s1[i];
            *(uint4*)(smemB + SOFF_VLO + row * ROWB + c * 16) = s2[i];
        }
    }
    __syncthreads();

    // hoist V fragments into registers (invariant across all rr)
    uint32_t vhi[4][4], vlo[4][4];
    load_afrags(vhi, sb + SOFF_VHI, m0, lane);
    load_afrags(vlo, sb + SOFF_VLO, m0, lane);

    // per-lane address offsets
    // trans (stage-1 B: A tile [v rows][h cols]): lanes pick k-rows, n-col halves
    const uint32_t toff = (uint32_t)(((lane >> 3) & 1) * 8 + (lane & 7)) * ROWB
                        + (uint32_t)((lane >> 4) << 3) * 2;
    // non-trans (stage-2 B: W2 tile [x rows][h cols])
    const uint32_t woff = (uint32_t)(((lane >> 4) << 3) + (lane & 7)) * ROWB
                        + (uint32_t)(((lane >> 3) & 1) << 3) * 2;

    float oc[8][4];
#pragma unroll
    for (int t = 0; t < 8; t++)
#pragma unroll
        for (int j = 0; j < 4; j++) oc[t][j] = 0.f;

    for (int rl = 0; rl < RRG; rl++) {
        const int rr = rr0 + ((rl + stag) & (RRG - 1));
        const uint32_t sbuf = sb + SOFF_BUF + (rl & 1) * BUFB;
        const uint32_t snxt = sb + SOFF_BUF + ((rl & 1) ^ 1) * BUFB;

        const float rsc0 = g_rT[(n * RD + rr) * IJ + token0 + m0 + mrow];
        const float rsc8 = g_rT[(n * RD + rr) * IJ + token0 + m0 + mrow + 8];

        __syncthreads();   // prev iter compute done (next buffer free)
        if (rl + 1 < RRG) {
            issue_fills(snxt, n, rr0 + ((rl + 1 + stag) & (RRG - 1)), h0g, tid);
            CP_COMMIT();
            CP_WAIT1();
        } else {
            CP_WAIT0();
        }
        __syncthreads();   // current buffer visible

        // ---- pipelined per h-chunk (16 cols): stage1 -> split -> stage2 ----
#pragma unroll
        for (int c2 = 0; c2 < 4; c2++) {
            float p0[4] = {0.f, 0.f, 0.f, 0.f};
            float p1[4] = {0.f, 0.f, 0.f, 0.f};
#pragma unroll
            for (int kk = 0; kk < 4; kk++) {     // k = v
                uint32_t b0, b1, b2, b3;
                ldsm4t(b0, b1, b2, b3, sbuf + toff + kk * 16 * ROWB + c2 * 32);
                mma_bf16(p0, vhi[kk], b0, b1);
                mma_bf16(p1, vhi[kk], b2, b3);
                mma_bf16(p0, vlo[kk], b0, b1);
                mma_bf16(p1, vlo[kk], b2, b3);
            }
#pragma unroll
            for (int kk = 0; kk < 4; kk++) {
                uint32_t b0, b1, b2, b3;
                ldsm4t(b0, b1, b2, b3, sbuf + TILEB + toff + kk * 16 * ROWB + c2 * 32);
                mma_bf16(p0, vhi[kk], b0, b1);
                mma_bf16(p1, vhi[kk], b2, b3);
            }

            // epilogue for this chunk: relu * r, split -> stage-2 A fragments
            uint32_t fhi[4], flo[4];
            split2(fmaxf(p0[0], 0.f) * rsc0, fmaxf(p0[1], 0.f) * rsc0, fhi[0], flo[0]);
            split2(fmaxf(p0[2], 0.f) * rsc8, fmaxf(p0[3], 0.f) * rsc8, fhi[1], flo[1]);
            split2(fmaxf(p1[0], 0.f) * rsc0, fmaxf(p1[1], 0.f) * rsc0, fhi[2], flo[2]);
            split2(fmaxf(p1[2], 0.f) * rsc8, fmaxf(p1[3], 0.f) * rsc8, fhi[3], flo[3]);

            // stage-2 partial: K-chunk c2
#pragma unroll
            for (int nt = 0; nt < 4; nt++) {     // x tiles
                uint32_t b0, b1, b2, b3;
                ldsm4(b0, b1, b2, b3, sbuf + 2 * TILEB + woff + nt * 16 * ROWB + c2 * 32);
                mma_bf16(oc[2 * nt],     fhi, b0, b1);
                mma_bf16(oc[2 * nt + 1], fhi, b2, b3);
                mma_bf16(oc[2 * nt],     flo, b0, b1);
                mma_bf16(oc[2 * nt + 1], flo, b2, b3);
                ldsm4(b0, b1, b2, b3, sbuf + 3 * TILEB + woff + nt * 16 * ROWB + c2 * 32);
                mma_bf16(oc[2 * nt],     fhi, b0, b1);
                mma_bf16(oc[2 * nt + 1], fhi, b2, b3);
            }
        }
    }

    // final epilogue: 4 partial CTAs per out element (2 hblk x 2 rr-halves)
    {
        float* op = out + (size_t)(n * IJ + token0 + m0 + mrow) * XD;
#pragma unroll
        for (int nt = 0; nt < 8; nt++) {
            const int x = nt * 8 + 2 * (lane & 3);
            atomicAdd(op + x,     oc[nt][0]);
            atomicAdd(op + x + 1, oc[nt][1]);
            atomicAdd(op + 8 * XD + x,     oc[nt][2]);
            atomicAdd(op + 8 * XD + x + 1, oc[nt][3]);
        }
    }
}

// ---------------------------------------------------------------------------
extern "C" void kernel_launch(void* const* d_in, const int* in_sizes, int n_in,
                              void* d_out, int out_size) {
    const float* r  = (const float*)d_in[0];
    const float* u  = (const float*)d_in[1];
    const float* v  = (const float*)d_in[2];
    const float* w1 = (const float*)d_in[3];
    const float* w2 = (const float*)d_in[4];
    float* out = (float*)d_out;
    (void)in_sizes; (void)n_in; (void)out_size;

    static int attr_done = 0;
    if (!attr_done) {
        cudaFuncSetAttribute(kernB, cudaFuncAttributeMaxDynamicSharedMemorySize, SMEM_TOTAL);
        attr_done = 1;
    }

    kernPre<<<1088, 256>>>(r, v, w2);
    kernA<<<dim3(RD, VD), 128>>>(u, w1, out);
    kernB<<<dim3(IJ / TM, NB, 4), 256, SMEM_TOTAL>>>(out);
}

// round 13
// speedup vs baseline: 3.1219x; 1.0032x over previous
#include <cuda_runtime.h>
#include <cuda_bf16.h>
#include <cstdint>

#define RD 64
#define UD 64
#define VD 64
#define HD 128
#define XD 64
#define NB 8
#define IJ 1024
#define TM 128           // token tile
#define HC 64            // h per CTA (hblk)
#define RRG 32           // rr per CTA

#define ROWB 144
#define VTILEB (128 * ROWB)        // 18432
#define TILEB  (64 * ROWB)         // 9216
#define SOFF_VHI 0
#define SOFF_VLO VTILEB
#define SOFF_BUF (2 * VTILEB)
#define BUFB (4 * TILEB)           // [AHI][ALO][WHI][WLO]
#define SMEM_TOTAL (2 * VTILEB + 2 * BUFB)   // 110592 -> 2 CTAs/SM

// ---------------- gmem scratch ----------------
__device__ float g_rT[NB * RD * IJ];                               // r^T, 2MB
__device__ __align__(16) unsigned short g_ahi[NB * RD * VD * HD];  // A split [n][rr][v][h]
__device__ __align__(16) unsigned short g_alo[NB * RD * VD * HD];
__device__ __align__(16) unsigned short g_vhi[NB * IJ * VD];       // V split [n][m][v]
__device__ __align__(16) unsigned short g_vlo[NB * IJ * VD];
__device__ __align__(16) unsigned short g_w2hi[RD * XD * HD];      // w2 split [rr][x][h]
__device__ __align__(16) unsigned short g_w2lo[RD * XD * HD];

// ---------------- helpers ----------------
__device__ __forceinline__ uint32_t smem_u32(const void* p) {
    uint32_t a;
    asm("{ .reg .u64 t; cvta.to.shared.u64 t, %1; cvt.u32.u64 %0, t; }" : "=r"(a) : "l"(p));
    return a;
}
__device__ __forceinline__ void cp16(uint32_t dst, const void* src) {
    asm volatile("cp.async.cg.shared.global [%0], [%1], 16;" :: "r"(dst), "l"(src));
}
#define CP_COMMIT() asm volatile("cp.async.commit_group;" ::: "memory")
#define CP_WAIT0()  asm volatile("cp.async.wait_group 0;" ::: "memory")

__device__ __forceinline__ void ldsm4(uint32_t& r0, uint32_t& r1, uint32_t& r2, uint32_t& r3,
                                      uint32_t addr) {
    asm volatile("ldmatrix.sync.aligned.m8n8.x4.shared.b16 {%0,%1,%2,%3}, [%4];"
                 : "=r"(r0), "=r"(r1), "=r"(r2), "=r"(r3) : "r"(addr));
}
__device__ __forceinline__ void ldsm4t(uint32_t& r0, uint32_t& r1, uint32_t& r2, uint32_t& r3,
                                       uint32_t addr) {
    asm volatile("ldmatrix.sync.aligned.m8n8.x4.trans.shared.b16 {%0,%1,%2,%3}, [%4];"
                 : "=r"(r0), "=r"(r1), "=r"(r2), "=r"(r3) : "r"(addr));
}
__device__ __forceinline__ void mma_bf16(float* d, const uint32_t a[4],
                                         uint32_t b0, uint32_t b1) {
    asm volatile(
        "mma.sync.aligned.m16n8k16.row.col.f32.bf16.bf16.f32 "
        "{%0,%1,%2,%3}, {%4,%5,%6,%7}, {%8,%9}, {%0,%1,%2,%3};"
        : "+f"(d[0]), "+f"(d[1]), "+f"(d[2]), "+f"(d[3])
        : "r"(a[0]), "r"(a[1]), "r"(a[2]), "r"(a[3]), "r"(b0), "r"(b1));
}
__device__ __forceinline__ void splitf(float x, unsigned short& hi, unsigned short& lo) {
    __nv_bfloat16 h = __float2bfloat16(x);
    __nv_bfloat16 l = __float2bfloat16(x - __bfloat162float(h));
    hi = __bfloat16_as_ushort(h);
    lo = __bfloat16_as_ushort(l);
}
__device__ __forceinline__ void split2(float p0, float p1, uint32_t& hp, uint32_t& lp) {
    asm("cvt.rn.bf16x2.f32 %0, %1, %2;" : "=r"(hp) : "f"(p1), "f"(p0));
    float h0 = __uint_as_float(hp << 16);
    float h1 = __uint_as_float(hp & 0xffff0000u);
    float l0 = p0 - h0, l1 = p1 - h1;
    asm("cvt.rn.bf16x2.f32 %0, %1, %2;" : "=r"(lp) : "f"(l1), "f"(l0));
}

__device__ __forceinline__ void load_afrags(uint32_t f[4][4], uint32_t abase, int m0, int lane) {
    const uint32_t aaddr = abase + (uint32_t)(m0 + (lane & 15)) * ROWB
                         + (uint32_t)((lane >> 4) << 3) * 2;
#pragma unroll
    for (int kk = 0; kk < 4; kk++)
        ldsm4(f[kk][0], f[kk][1], f[kk][2], f[kk][3], aaddr + kk * 32);
}

// ---------------------------------------------------------------------------
// kernPre: merged r-transpose / V-split / w2-split
// ---------------------------------------------------------------------------
__global__ __launch_bounds__(256) void kernPre(const float* __restrict__ r,
                                               const float* __restrict__ v,
                                               const float* __restrict__ w2) {
    const int b = blockIdx.x;
    if (b < 512) {
        const int n = b >> 6, rr = b & 63;
        for (int t = threadIdx.x; t < IJ; t += 256)
            g_rT[(n * RD + rr) * IJ + t] = r[(n * IJ + t) * RD + rr];
    } else if (b < 1024) {
        for (int i = (b - 512) * 256 + threadIdx.x; i < NB * IJ * VD; i += 512 * 256) {
            unsigned short hi, lo;
            splitf(v[i], hi, lo);
            g_vhi[i] = hi;
            g_vlo[i] = lo;
        }
    } else {
        const int rr = b - 1024;
        const int h = threadIdx.x & 127;
        for (int x = threadIdx.x >> 7; x < XD; x += 2) {
            unsigned short hi, lo;
            splitf(w2[(x * RD + rr) * HD + h], hi, lo);
            g_w2hi[(rr * XD + x) * HD + h] = hi;
            g_w2lo[(rr * XD + x) * HD + h] = lo;
        }
    }
}

// ---------------------------------------------------------------------------
// kernA: A[n,rr,v,h] = sum_u w1*u, split bf16 -> g_ahi/lo[n][rr][v][h].
// grid (64 rr, 16 v-groups), 128 thr: warp <-> one vv, thread <-> 4 h (float4).
// Full 512B rows per warp-load; 2KB contiguous across the 4 warps. Zeroes out.
// ---------------------------------------------------------------------------
__global__ __launch_bounds__(128) void kernA(const float* __restrict__ u,
                                             const float* __restrict__ w1,
                                             float* __restrict__ out) {
    const int rr = blockIdx.x;
    const int vv0 = blockIdx.y * 4;
    const int t = threadIdx.x;
    const int vloc = t >> 5;                 // 0..3 (warp id)
    const int h4 = (t & 31) * 4;             // 0..124
    const int vv = vv0 + vloc;

    // zero out: 1024 CTAs x 128 thr x 4 floats = 524288
    *(float4*)&out[(size_t)((blockIdx.y * RD + blockIdx.x) * 128 + t) * 4] =
        make_float4(0.f, 0.f, 0.f, 0.f);

    __shared__ float us[4][NB][UD];          // [vloc][n][uu]
    for (int idx = t; idx < NB * UD; idx += 128) {
        int n = idx >> 6, uu = idx & 63;
        float4 uv = *(const float4*)&u[((n * RD + rr) * UD + uu) * VD + vv0];
        us[0][n][uu] = uv.x;
        us[1][n][uu] = uv.y;
        us[2][n][uu] = uv.z;
        us[3][n][uu] = uv.w;
    }
    __syncthreads();

    float acc[NB][4];
#pragma unroll
    for (int n = 0; n < NB; n++)
#pragma unroll
        for (int j = 0; j < 4; j++) acc[n][j] = 0.f;

    const float* w1p = w1 + ((size_t)(rr * UD) * VD + vv) * HD + h4;
#pragma unroll 8
    for (int uu = 0; uu < UD; uu++) {
        float4 wv = *(const float4*)(w1p + (size_t)uu * (VD * HD));
#pragma unroll
        for (int n = 0; n < NB; n++) {
            float s = us[vloc][n][uu];
            acc[n][0] = fmaf(wv.x, s, acc[n][0]);
            acc[n][1] = fmaf(wv.y, s, acc[n][1]);
            acc[n][2] = fmaf(wv.z, s, acc[n][2]);
            acc[n][3] = fmaf(wv.w, s, acc[n][3]);
        }
    }
#pragma unroll
    for (int n = 0; n < NB; n++) {
        ushort4 hi4, lo4;
        splitf(acc[n][0], hi4.x, lo4.x);
        splitf(acc[n][1], hi4.y, lo4.y);
        splitf(acc[n][2], hi4.z, lo4.z);
        splitf(acc[n][3], hi4.w, lo4.w);
        const size_t o = ((size_t)(n * RD + rr) * VD + vv) * HD + h4;
        *(ushort4*)&g_ahi[o] = hi4;
        *(ushort4*)&g_alo[o] = lo4;
    }
}

// ---------------------------------------------------------------------------
// kernB: 256 thr, tile 128m x 64c, single-barrier cp.async pipeline.
// ---------------------------------------------------------------------------
extern __shared__ unsigned char smemB[];

__device__ __forceinline__ void issue_fills(uint32_t sbuf, int n, int rr, int h0g, int tid) {
    const unsigned short* a1 = g_ahi + ((size_t)(n * RD + rr) * VD) * HD + h0g;
    const unsigned short* a2 = g_alo + ((size_t)(n * RD + rr) * VD) * HD + h0g;
#pragma unroll
    for (int j = 0; j < 2; j++) {
        int i = tid + j * 256;               // 0..511
        int row = i >> 3, c = i & 7;
        uint32_t dst = sbuf + row * ROWB + c * 16;
        cp16(dst,             a1 + (size_t)row * HD + c * 8);
        cp16(dst + TILEB,     a2 + (size_t)row * HD + c * 8);
        const unsigned short* w1p = g_w2hi + (size_t)(rr * XD + row) * HD + h0g + c * 8;
        const unsigned short* w2p = g_w2lo + (size_t)(rr * XD + row) * HD + h0g + c * 8;
        cp16(dst + 2 * TILEB, w1p);
        cp16(dst + 3 * TILEB, w2p);
    }
}

__global__ __launch_bounds__(256, 2) void kernB(float* __restrict__ out) {
    const uint32_t sb = smem_u32(smemB);
    const int tid = threadIdx.x, lane = tid & 31, w = tid >> 5;
    const int tile = blockIdx.x, n = blockIdx.y, z = blockIdx.z;
    const int token0 = tile * TM;
    const int h0g = (z & 1) * HC;
    const int rr0 = (z >> 1) * RRG;
    const int m0 = w * 16;
    const int mrow = lane >> 2;
    const int stag = (blockIdx.x & 1) * (RRG / 2);

    // prefetch first rr into buffer 0
    issue_fills(sb + SOFF_BUF, n, rr0 + stag, h0g, tid);
    CP_COMMIT();

    // V tile fill (once)
    {
        const uint4* s1 = (const uint4*)(g_vhi + (size_t)(n * IJ + token0) * VD);
        const uint4* s2 = (const uint4*)(g_vlo + (size_t)(n * IJ + token0) * VD);
#pragma unroll
        for (int j = 0; j < 4; j++) {
            int i = tid + j * 256;
            int row = i >> 3, c = i & 7;
            *(uint4*)(smemB + SOFF_VHI + row * ROWB + c * 16) = s1[i];
            *(uint4*)(smemB + SOFF_VLO + row * ROWB + c * 16) = s2[i];
        }
    }
    __syncthreads();

    uint32_t vhi[4][4], vlo[4][4];
    load_afrags(vhi, sb + SOFF_VHI, m0, lane);
    load_afrags(vlo, sb + SOFF_VLO, m0, lane);

    const uint32_t toff = (uint32_t)(((lane >> 3) & 1) * 8 + (lane & 7)) * ROWB
                        + (uint32_t)((lane >> 4) << 3) * 2;
    const uint32_t woff = (uint32_t)(((lane >> 4) << 3) + (lane & 7)) * ROWB
                        + (uint32_t)(((lane >> 3) & 1) << 3) * 2;

    float oc[8][4];
#pragma unroll
    for (int t = 0; t < 8; t++)
#pragma unroll
        for (int j = 0; j < 4; j++) oc[t][j] = 0.f;

    for (int rl = 0; rl < RRG; rl++) {
        const int rr = rr0 + ((rl + stag) & (RRG - 1));
        const uint32_t sbuf = sb + SOFF_BUF + (rl & 1) * BUFB;

        const float rsc0 = g_rT[(n * RD + rr) * IJ + token0 + m0 + mrow];
        const float rsc8 = g_rT[(n * RD + rr) * IJ + token0 + m0 + mrow + 8];

        CP_WAIT0();        // buffer rl arrived (had full previous compute span)
        __syncthreads();   // publish buffer rl; all warps done consuming rl-1
        if (rl + 1 < RRG) {
            issue_fills(sb + SOFF_BUF + ((rl & 1) ^ 1) * BUFB,
                        n, rr0 + ((rl + 1 + stag) & (RRG - 1)), h0g, tid);
            CP_COMMIT();
        }

        // ---- pipelined per h-chunk: stage1 -> split -> stage2 ----
#pragma unroll
        for (int c2 = 0; c2 < 4; c2++) {
            float p0[4] = {0.f, 0.f, 0.f, 0.f};
            float p1[4] = {0.f, 0.f, 0.f, 0.f};
#pragma unroll
            for (int kk = 0; kk < 4; kk++) {
                uint32_t b0, b1, b2, b3;
                ldsm4t(b0, b1, b2, b3, sbuf + toff + kk * 16 * ROWB + c2 * 32);
                mma_bf16(p0, vhi[kk], b0, b1);
                mma_bf16(p1, vhi[kk], b2, b3);
                mma_bf16(p0, vlo[kk], b0, b1);
                mma_bf16(p1, vlo[kk], b2, b3);
            }
#pragma unroll
            for (int kk = 0; kk < 4; kk++) {
                uint32_t b0, b1, b2, b3;
                ldsm4t(b0, b1, b2, b3, sbuf + TILEB + toff + kk * 16 * ROWB + c2 * 32);
                mma_bf16(p0, vhi[kk], b0, b1);
                mma_bf16(p1, vhi[kk], b2, b3);
            }

            uint32_t fhi[4], flo[4];
            split2(fmaxf(p0[0], 0.f) * rsc0, fmaxf(p0[1], 0.f) * rsc0, fhi[0], flo[0]);
            split2(fmaxf(p0[2], 0.f) * rsc8, fmaxf(p0[3], 0.f) * rsc8, fhi[1], flo[1]);
            split2(fmaxf(p1[0], 0.f) * rsc0, fmaxf(p1[1], 0.f) * rsc0, fhi[2], flo[2]);
            split2(fmaxf(p1[2], 0.f) * rsc8, fmaxf(p1[3], 0.f) * rsc8, fhi[3], flo[3]);

#pragma unroll
            for (int nt = 0; nt < 4; nt++) {
                uint32_t b0, b1, b2, b3;
                ldsm4(b0, b1, b2, b3, sbuf + 2 * TILEB + woff + nt * 16 * ROWB + c2 * 32);
                mma_bf16(oc[2 * nt],     fhi, b0, b1);
                mma_bf16(oc[2 * nt + 1], fhi, b2, b3);
                mma_bf16(oc[2 * nt],     flo, b0, b1);
                mma_bf16(oc[2 * nt + 1], flo, b2, b3);
                ldsm4(b0, b1, b2, b3, sbuf + 3 * TILEB + woff + nt * 16 * ROWB + c2 * 32);
                mma_bf16(oc[2 * nt],     fhi, b0, b1);
                mma_bf16(oc[2 * nt + 1], fhi, b2, b3);
            }
        }
    }

    // final epilogue: 4 partial CTAs per out element
    {
        float* op = out + (size_t)(n * IJ + token0 + m0 + mrow) * XD;
#pragma unroll
        for (int nt = 0; nt < 8; nt++) {
            const int x = nt * 8 + 2 * (lane & 3);
            atomicAdd(op + x,     oc[nt][0]);
            atomicAdd(op + x + 1, oc[nt][1]);
            atomicAdd(op + 8 * XD + x,     oc[nt][2]);
            atomicAdd(op + 8 * XD + x + 1, oc[nt][3]);
        }
    }
}

// ---------------------------------------------------------------------------
extern "C" void kernel_launch(void* const* d_in, const int* in_sizes, int n_in,
                              void* d_out, int out_size) {
    const float* r  = (const float*)d_in[0];
    const float* u  = (const float*)d_in[1];
    const float* v  = (const float*)d_in[2];
    const float* w1 = (const float*)d_in[3];
    const float* w2 = (const float*)d_in[4];
    float* out = (float*)d_out;
    (void)in_sizes; (void)n_in; (void)out_size;

    static int attr_done = 0;
    if (!attr_done) {
        cudaFuncSetAttribute(kernB, cudaFuncAttributeMaxDynamicSharedMemorySize, SMEM_TOTAL);
        attr_done = 1;
    }

    kernPre<<<1088, 256>>>(r, v, w2);
    kernA<<<dim3(RD, 16), 128>>>(u, w1, out);
    kernB<<<dim3(IJ / TM, NB, 4), 256, SMEM_TOTAL>>>(out);
}